// round 4
// baseline (speedup 1.0000x reference)
#include <cuda_runtime.h>

// ----------------------------------------------------------------------------
// RelativeAttention2d  (B=16, C=256, H=32 -> N=1024 tokens, HEADS=8, HS=32)
//
// All torch reshapes in the reference are RAW views, so per batch everything
// lives in one flat 262144-float buffer viewed as M=[1024][256]:
//   Q_h[d,m] = QL[h*128 + 4d + (m>>8)][m & 255]   (same for K, V, and O)
// rel_idx is recomputed analytically:  (yn-ym+31)*63 + (xn-xm+31).
// Softmax is over the key axis; logits are bounded (~|7|) so no max-subtract.
// ----------------------------------------------------------------------------

namespace {
constexpr int BATCH = 16;
constexpr int PB    = 256 * 1024;   // per-batch elements (C*H*W = N*C)
}

__device__ float g_xn[BATCH * PB];
__device__ float g_q [BATCH * PB];
__device__ float g_k [BATCH * PB];
__device__ float g_v [BATCH * PB];
__device__ float g_o [BATCH * PB];

// ------------------------------ LayerNorm -----------------------------------
// grid(4, 16), block 256. One thread per spatial position p, reduce over C=256
// channels (stride 1024, coalesced across threads).
__global__ __launch_bounds__(256) void ln_kernel(const float* __restrict__ x,
                                                 const float* __restrict__ gamma,
                                                 const float* __restrict__ beta) {
    __shared__ float sg[256];
    __shared__ float sb[256];
    const int tid = threadIdx.x;
    sg[tid] = gamma[tid];
    sb[tid] = beta[tid];
    __syncthreads();

    const int b = blockIdx.y;
    const int p = blockIdx.x * 256 + tid;
    const float* xb = x + b * PB;

    float s = 0.f, ss = 0.f;
#pragma unroll 8
    for (int c = 0; c < 256; c++) {
        const float v = xb[c * 1024 + p];
        s += v;
        ss += v * v;
    }
    const float mu  = s * (1.0f / 256.0f);
    const float var = ss * (1.0f / 256.0f) - mu * mu;
    const float r   = rsqrtf(var + 1e-5f);

    float* ob = g_xn + b * PB;
#pragma unroll 8
    for (int c = 0; c < 256; c++) {
        const float v = xb[c * 1024 + p];
        ob[c * 1024 + p] = (v - mu) * r * sg[c] + sb[c];
    }
}

// ------------------------------ GEMM ----------------------------------------
// C[n][d] = sum_k A[n][k] * W[d][k] + bias[d]  (+ optional residual R)
// A: [1024][256] per batch, W: [256][256].  64x64 tile, 256 thr, 4x4 micro.
// grid(4, 16, BATCH)
__global__ __launch_bounds__(256) void gemm_kernel(const float* __restrict__ Abase,
                                                   const float* __restrict__ W,
                                                   const float* __restrict__ bias,
                                                   float* __restrict__ Cbase,
                                                   const float* __restrict__ Rbase) {
    __shared__ float As[16][68];
    __shared__ float Bs[16][68];

    const int b  = blockIdx.z;
    const float* A = Abase + b * PB;
    float*      Cc = Cbase + b * PB;
    const int n0 = blockIdx.y * 64;
    const int d0 = blockIdx.x * 64;
    const int tid = threadIdx.x;
    const int tx = tid & 15;
    const int ty = tid >> 4;
    const int ln = tid >> 2;
    const int lk = (tid & 3) * 4;

    float acc[4][4];
#pragma unroll
    for (int i = 0; i < 4; i++)
#pragma unroll
        for (int j = 0; j < 4; j++) acc[i][j] = 0.f;

    for (int k0 = 0; k0 < 256; k0 += 16) {
        const float4 a4 = *(const float4*)&A[(n0 + ln) * 256 + k0 + lk];
        const float4 b4 = *(const float4*)&W[(d0 + ln) * 256 + k0 + lk];
        As[lk + 0][ln] = a4.x; As[lk + 1][ln] = a4.y;
        As[lk + 2][ln] = a4.z; As[lk + 3][ln] = a4.w;
        Bs[lk + 0][ln] = b4.x; Bs[lk + 1][ln] = b4.y;
        Bs[lk + 2][ln] = b4.z; Bs[lk + 3][ln] = b4.w;
        __syncthreads();

#pragma unroll
        for (int kk = 0; kk < 16; kk++) {
            const float4 av = *(const float4*)&As[kk][ty * 4];
            const float4 bv = *(const float4*)&Bs[kk][tx * 4];
            const float ar[4] = {av.x, av.y, av.z, av.w};
            const float br[4] = {bv.x, bv.y, bv.z, bv.w};
#pragma unroll
            for (int i = 0; i < 4; i++)
#pragma unroll
                for (int j = 0; j < 4; j++)
                    acc[i][j] = fmaf(ar[i], br[j], acc[i][j]);
        }
        __syncthreads();
    }

    const int col = d0 + tx * 4;
    const float4 bi = *(const float4*)&bias[col];
#pragma unroll
    for (int i = 0; i < 4; i++) {
        const int row = n0 + ty * 4 + i;
        float4 ov = make_float4(acc[i][0] + bi.x, acc[i][1] + bi.y,
                                acc[i][2] + bi.z, acc[i][3] + bi.w);
        if (Rbase != nullptr) {
            const float4 r4 = *(const float4*)&Rbase[b * PB + row * 256 + col];
            ov.x += r4.x; ov.y += r4.y; ov.z += r4.z; ov.w += r4.w;
        }
        *(float4*)&Cc[row * 256 + col] = ov;
    }
}

// ------------------------------ Attention -----------------------------------
// One CTA = (b, h, 64-query tile). Loops over 16 key tiles of 64.
// Phase A: S = K^T Q /16 + bias, P = exp(S) -> smem, column sums -> rsum.
// Phase B: O[d][m] += V P (register accumulators).  Final: O /= rsum, write OL.
// Smem (floats): relb 3972 | Kt 2048 | Qt 2048 | Vt 2048 | St 64*68 | rsum 64
__global__ __launch_bounds__(256) void attn_kernel(const float* __restrict__ rel_bias) {
    extern __shared__ float sm[];
    float* relb = sm;            // 3969 (+3 pad)
    float* Kt   = sm + 3972;     // [32][64]  (d-major)
    float* Qt   = sm + 6020;     // [32][64]
    float* Vt   = sm + 8068;     // [32][64]
    float* St   = sm + 10116;    // [64][68]  (n-major, exp'd probs)
    float* rsum = sm + 14468;    // [64]

    const int tid = threadIdx.x;
    const int m0  = blockIdx.x * 64;
    const int h   = blockIdx.y;
    const int b   = blockIdx.z;

    const float* QL = g_q + b * PB;
    const float* KL = g_k + b * PB;
    const float* VL = g_v + b * PB;
    float*       OL = g_o + b * PB;

    // per-head relative-bias table into smem
    const float* rb = rel_bias + h * 3969;
    for (int i = tid; i < 3969; i += 256) relb[i] = rb[i];
    if (tid < 64) rsum[tid] = 0.0f;

    const int jblk = m0 >> 8;       // which 256-col block of QL this m-tile is in
    const int mc0  = m0 & 255;
    {   // load Q tile: Qt[d][ml]
        const int d   = tid >> 3;
        const int off = (tid & 7) * 8;
        const float* src = QL + (h * 128 + 4 * d + jblk) * 256 + mc0 + off;
        const float4 v0 = *(const float4*)(src);
        const float4 v1 = *(const float4*)(src + 4);
        *(float4*)&Qt[d * 64 + off]     = v0;
        *(float4*)&Qt[d * 64 + off + 4] = v1;
    }
    __syncthreads();

    const int tx = tid & 15;        // phase A: n-group   (n = 4*tx + i)
    const int ty = tid >> 4;        // phase A: m-group   (m = 4*ty + j)
    const int od = ty * 2;          // phase B: d pair
    const int om = tx * 4;          // phase B: m quad

    float o0[4] = {0.f, 0.f, 0.f, 0.f};
    float o1[4] = {0.f, 0.f, 0.f, 0.f};

    int ym[4], xm[4];
#pragma unroll
    for (int j = 0; j < 4; j++) {
        const int mm = m0 + 4 * ty + j;
        ym[j] = mm >> 5;
        xm[j] = mm & 31;
    }

    for (int nt = 0; nt < 16; nt++) {
        const int n0   = nt * 64;
        const int iblk = n0 >> 8;
        const int nc0  = n0 & 255;
        {   // load K, V tiles (d-major, coalesced rows of 64)
            const int d   = tid >> 3;
            const int off = (tid & 7) * 8;
            const float* ks = KL + (h * 128 + 4 * d + iblk) * 256 + nc0 + off;
            const float* vs = VL + (h * 128 + 4 * d + iblk) * 256 + nc0 + off;
            const float4 a0 = *(const float4*)(ks);
            const float4 a1 = *(const float4*)(ks + 4);
            const float4 c0 = *(const float4*)(vs);
            const float4 c1 = *(const float4*)(vs + 4);
            *(float4*)&Kt[d * 64 + off]     = a0;
            *(float4*)&Kt[d * 64 + off + 4] = a1;
            *(float4*)&Vt[d * 64 + off]     = c0;
            *(float4*)&Vt[d * 64 + off + 4] = c1;
        }
        __syncthreads();

        // ---- Phase A: S = K^T Q over d=0..31, 4x4 register tile -------------
        float s[4][4];
#pragma unroll
        for (int i = 0; i < 4; i++)
#pragma unroll
            for (int j = 0; j < 4; j++) s[i][j] = 0.f;

#pragma unroll
        for (int d = 0; d < 32; d++) {
            const float4 kv = *(const float4*)&Kt[d * 64 + 4 * tx];
            const float4 qv = *(const float4*)&Qt[d * 64 + 4 * ty];
            const float ka[4] = {kv.x, kv.y, kv.z, kv.w};
            const float qa[4] = {qv.x, qv.y, qv.z, qv.w};
#pragma unroll
            for (int i = 0; i < 4; i++)
#pragma unroll
                for (int j = 0; j < 4; j++)
                    s[i][j] = fmaf(ka[i], qa[j], s[i][j]);
        }

        // bias (analytic rel_idx) + exp + store P + column partial sums
        float cs[4] = {0.f, 0.f, 0.f, 0.f};
#pragma unroll
        for (int i = 0; i < 4; i++) {
            const int ng = n0 + 4 * tx + i;
            const int yn = ng >> 5, xn = ng & 31;
            float p[4];
#pragma unroll
            for (int j = 0; j < 4; j++) {
                const float bias = relb[(yn - ym[j] + 31) * 63 + (xn - xm[j] + 31)];
                p[j] = __expf(fmaf(s[i][j], 0.0625f, bias));
                cs[j] += p[j];
            }
            *(float4*)&St[(4 * tx + i) * 68 + 4 * ty] = make_float4(p[0], p[1], p[2], p[3]);
        }
#pragma unroll
        for (int offr = 8; offr >= 1; offr >>= 1) {
#pragma unroll
            for (int j = 0; j < 4; j++)
                cs[j] += __shfl_down_sync(0xffffffffu, cs[j], offr, 16);
        }
        if (tx == 0) {
#pragma unroll
            for (int j = 0; j < 4; j++) rsum[4 * ty + j] += cs[j];
        }
        __syncthreads();

        // ---- Phase B: O[d][m] += V[d][n] * P[n][m] --------------------------
#pragma unroll 4
        for (int n = 0; n < 64; n++) {
            const float v0 = Vt[od * 64 + n];
            const float v1 = Vt[(od + 1) * 64 + n];
            const float4 p4 = *(const float4*)&St[n * 68 + om];
            o0[0] = fmaf(v0, p4.x, o0[0]);
            o0[1] = fmaf(v0, p4.y, o0[1]);
            o0[2] = fmaf(v0, p4.z, o0[2]);
            o0[3] = fmaf(v0, p4.w, o0[3]);
            o1[0] = fmaf(v1, p4.x, o1[0]);
            o1[1] = fmaf(v1, p4.y, o1[1]);
            o1[2] = fmaf(v1, p4.z, o1[2]);
            o1[3] = fmaf(v1, p4.w, o1[3]);
        }
        __syncthreads();
    }

    if (tid < 64) rsum[tid] = 1.0f / rsum[tid];
    __syncthreads();

    const float4 rv = *(const float4*)&rsum[om];
    const int row0 = h * 128 + 4 * od + jblk;
    const int row1 = h * 128 + 4 * (od + 1) + jblk;
    const float4 w0 = make_float4(o0[0] * rv.x, o0[1] * rv.y, o0[2] * rv.z, o0[3] * rv.w);
    const float4 w1 = make_float4(o1[0] * rv.x, o1[1] * rv.y, o1[2] * rv.z, o1[3] * rv.w);
    *(float4*)&OL[row0 * 256 + mc0 + om] = w0;
    *(float4*)&OL[row1 * 256 + mc0 + om] = w1;
}

// ------------------------------ Launch --------------------------------------
extern "C" void kernel_launch(void* const* d_in, const int* in_sizes, int n_in,
                              void* d_out, int out_size) {
    const float* x        = (const float*)d_in[0];
    const float* ln_g     = (const float*)d_in[1];
    const float* ln_b     = (const float*)d_in[2];
    const float* wq       = (const float*)d_in[3];
    const float* bq       = (const float*)d_in[4];
    const float* wk       = (const float*)d_in[5];
    const float* bk       = (const float*)d_in[6];
    const float* wv       = (const float*)d_in[7];
    const float* bv       = (const float*)d_in[8];
    const float* wo       = (const float*)d_in[9];
    const float* bo       = (const float*)d_in[10];
    const float* rel_bias = (const float*)d_in[11];
    // d_in[12] (rel_idx) intentionally unused: recomputed analytically in-kernel
    float* out = (float*)d_out;
    (void)in_sizes; (void)n_in; (void)out_size;

    float *p_xn, *p_q, *p_k, *p_v, *p_o;
    cudaGetSymbolAddress((void**)&p_xn, g_xn);
    cudaGetSymbolAddress((void**)&p_q,  g_q);
    cudaGetSymbolAddress((void**)&p_k,  g_k);
    cudaGetSymbolAddress((void**)&p_v,  g_v);
    cudaGetSymbolAddress((void**)&p_o,  g_o);

    ln_kernel<<<dim3(4, BATCH), 256>>>(x, ln_g, ln_b);

    const dim3 ggrid(4, 16, BATCH);
    gemm_kernel<<<ggrid, 256>>>(p_xn, wq, bq, p_q, nullptr);
    gemm_kernel<<<ggrid, 256>>>(p_xn, wk, bk, p_k, nullptr);
    gemm_kernel<<<ggrid, 256>>>(p_xn, wv, bv, p_v, nullptr);

    const int smem_bytes = 14532 * (int)sizeof(float);  // 58128 B
    cudaFuncSetAttribute((const void*)attn_kernel,
                         cudaFuncAttributeMaxDynamicSharedMemorySize, smem_bytes);
    attn_kernel<<<dim3(16, 8, BATCH), 256, smem_bytes>>>(rel_bias);

    gemm_kernel<<<ggrid, 256>>>(p_o, wo, bo, out, x);
}

// round 7
// speedup vs baseline: 1.0338x; 1.0338x over previous
#include <cuda_runtime.h>

// ----------------------------------------------------------------------------
// RelativeAttention2d  (B=16, C=256, H=32 -> N=1024 tokens, HEADS=8, HS=32)
// Round 2: packed fp32x2 FFMA (fma.rn.f32x2) + larger micro-tiles.
//   Flat-view trick: Q_h[d,m] = QL[h*128 + 4d + (m>>8)][m & 255]
//   rel_idx analytic: (yn-ym+31)*63 + (xn-xm+31)
//   Softmax over keys; logits bounded, no max-subtract needed.
// ----------------------------------------------------------------------------

namespace {
constexpr int BATCH = 16;
constexpr int PB    = 256 * 1024;
}

typedef unsigned long long ull;

__device__ float g_xn[BATCH * PB];
__device__ float g_q [BATCH * PB];
__device__ float g_k [BATCH * PB];
__device__ float g_v [BATCH * PB];
__device__ float g_o [BATCH * PB];

// ---------------------------- f32x2 helpers ---------------------------------
__device__ __forceinline__ ull pack2(float lo, float hi) {
    ull r;
    asm("mov.b64 %0, {%1, %2};" : "=l"(r) : "f"(lo), "f"(hi));
    return r;
}
__device__ __forceinline__ float2 unpack2(ull v) {
    float2 f;
    asm("mov.b64 {%0, %1}, %2;" : "=f"(f.x), "=f"(f.y) : "l"(v));
    return f;
}
__device__ __forceinline__ ull ffma2(ull a, ull b, ull c) {
    ull d;
    asm("fma.rn.f32x2 %0, %1, %2, %3;" : "=l"(d) : "l"(a), "l"(b), "l"(c));
    return d;
}
__device__ __forceinline__ ull fadd2(ull a, ull b) {
    ull d;
    asm("add.rn.f32x2 %0, %1, %2;" : "=l"(d) : "l"(a), "l"(b));
    return d;
}
// 128-bit shared load straight into two packed f32 pairs
__device__ __forceinline__ void lds_2u64(ull& a, ull& b, const float* p) {
    unsigned addr = (unsigned)__cvta_generic_to_shared(p);
    asm("ld.shared.v2.u64 {%0, %1}, [%2];" : "=l"(a), "=l"(b) : "r"(addr));
}

// ------------------------------ LayerNorm -----------------------------------
__global__ __launch_bounds__(256) void ln_kernel(const float* __restrict__ x,
                                                 const float* __restrict__ gamma,
                                                 const float* __restrict__ beta) {
    __shared__ float sg[256];
    __shared__ float sb[256];
    const int tid = threadIdx.x;
    sg[tid] = gamma[tid];
    sb[tid] = beta[tid];
    __syncthreads();

    const int b = blockIdx.y;
    const int p = blockIdx.x * 256 + tid;
    const float* xb = x + b * PB;

    float s = 0.f, ss = 0.f;
#pragma unroll 8
    for (int c = 0; c < 256; c++) {
        const float v = xb[c * 1024 + p];
        s += v;
        ss += v * v;
    }
    const float mu  = s * (1.0f / 256.0f);
    const float var = ss * (1.0f / 256.0f) - mu * mu;
    const float r   = rsqrtf(var + 1e-5f);

    float* ob = g_xn + b * PB;
#pragma unroll 8
    for (int c = 0; c < 256; c++) {
        const float v = xb[c * 1024 + p];
        ob[c * 1024 + p] = (v - mu) * r * sg[c] + sb[c];
    }
}

// ------------------------------ GEMM ----------------------------------------
// C[n][d] = sum_k A[n][k]*W[d][k] + bias[d] (+residual).  128x128 tile,
// 256 threads, 8x8 micro via fp32x2 FMA.  grid(2, 8, BATCH).
__global__ __launch_bounds__(256, 2) void gemm_kernel(const float* __restrict__ Abase,
                                                      const float* __restrict__ W,
                                                      const float* __restrict__ bias,
                                                      float* __restrict__ Cbase,
                                                      const float* __restrict__ Rbase) {
    __shared__ float As[16][132];
    __shared__ float Bs[16][132];

    const int b   = blockIdx.z;
    const float* A = Abase + b * PB;
    float*      Cc = Cbase + b * PB;
    const int n0  = blockIdx.y * 128;
    const int d0  = blockIdx.x * 128;
    const int tid = threadIdx.x;
    const int tx8 = (tid & 15) * 8;
    const int ty8 = (tid >> 4) * 8;
    const int lr  = tid >> 1;          // row 0..127 of the tile
    const int lc  = (tid & 1) * 8;     // k offset 0 or 8

    ull acc[8][4];
#pragma unroll
    for (int i = 0; i < 8; i++)
#pragma unroll
        for (int p = 0; p < 4; p++) acc[i][p] = 0ull;

    for (int k0 = 0; k0 < 256; k0 += 16) {
        const float4 a0 = *(const float4*)&A[(n0 + lr) * 256 + k0 + lc];
        const float4 a1 = *(const float4*)&A[(n0 + lr) * 256 + k0 + lc + 4];
        const float4 b0 = *(const float4*)&W[(d0 + lr) * 256 + k0 + lc];
        const float4 b1 = *(const float4*)&W[(d0 + lr) * 256 + k0 + lc + 4];
        As[lc + 0][lr] = a0.x; As[lc + 1][lr] = a0.y; As[lc + 2][lr] = a0.z; As[lc + 3][lr] = a0.w;
        As[lc + 4][lr] = a1.x; As[lc + 5][lr] = a1.y; As[lc + 6][lr] = a1.z; As[lc + 7][lr] = a1.w;
        Bs[lc + 0][lr] = b0.x; Bs[lc + 1][lr] = b0.y; Bs[lc + 2][lr] = b0.z; Bs[lc + 3][lr] = b0.w;
        Bs[lc + 4][lr] = b1.x; Bs[lc + 5][lr] = b1.y; Bs[lc + 6][lr] = b1.z; Bs[lc + 7][lr] = b1.w;
        __syncthreads();

#pragma unroll
        for (int kk = 0; kk < 16; kk++) {
            const float4 av0 = *(const float4*)&As[kk][ty8];
            const float4 av1 = *(const float4*)&As[kk][ty8 + 4];
            ull bv[4];
            lds_2u64(bv[0], bv[1], &Bs[kk][tx8]);
            lds_2u64(bv[2], bv[3], &Bs[kk][tx8 + 4]);
            ull asp[8];
            asp[0] = pack2(av0.x, av0.x); asp[1] = pack2(av0.y, av0.y);
            asp[2] = pack2(av0.z, av0.z); asp[3] = pack2(av0.w, av0.w);
            asp[4] = pack2(av1.x, av1.x); asp[5] = pack2(av1.y, av1.y);
            asp[6] = pack2(av1.z, av1.z); asp[7] = pack2(av1.w, av1.w);
#pragma unroll
            for (int i = 0; i < 8; i++)
#pragma unroll
                for (int p = 0; p < 4; p++)
                    acc[i][p] = ffma2(asp[i], bv[p], acc[i][p]);
        }
        __syncthreads();
    }

    const int col = d0 + tx8;
    const float4 bi0 = *(const float4*)&bias[col];
    const float4 bi1 = *(const float4*)&bias[col + 4];
#pragma unroll
    for (int i = 0; i < 8; i++) {
        const int row = n0 + ty8 + i;
        const float2 f0 = unpack2(acc[i][0]);
        const float2 f1 = unpack2(acc[i][1]);
        const float2 f2 = unpack2(acc[i][2]);
        const float2 f3 = unpack2(acc[i][3]);
        float4 w0 = make_float4(f0.x + bi0.x, f0.y + bi0.y, f1.x + bi0.z, f1.y + bi0.w);
        float4 w1 = make_float4(f2.x + bi1.x, f2.y + bi1.y, f3.x + bi1.z, f3.y + bi1.w);
        if (Rbase != nullptr) {
            const float4 r0 = *(const float4*)&Rbase[b * PB + row * 256 + col];
            const float4 r1 = *(const float4*)&Rbase[b * PB + row * 256 + col + 4];
            w0.x += r0.x; w0.y += r0.y; w0.z += r0.z; w0.w += r0.w;
            w1.x += r1.x; w1.y += r1.y; w1.z += r1.z; w1.w += r1.w;
        }
        *(float4*)&Cc[row * 256 + col]     = w0;
        *(float4*)&Cc[row * 256 + col + 4] = w1;
    }
}

// ------------------------------ Attention -----------------------------------
// One CTA = (b, h, 128-query tile); 16 key tiles of 64.
// Phase A: S = K^T Q, bias+exp -> St[64][132]; per-thread column partials kept
//          in registers across all tiles (one atomicAdd pass at the end).
// Phase B: O += V @ P with a 2-way n-split (thread halves), 4d x 8m micro.
// Smem floats: relb 3972 | Qt[32][128] | Kt[32][64] | Vt[32][64] | St[64][132] | rsum[128]
__global__ __launch_bounds__(256, 2) void attn_kernel(const float* __restrict__ rel_bias) {
    extern __shared__ float sm[];
    float* relb = sm;             // 3969 (+3 pad)
    float* Qt   = sm + 3972;      // 4096
    float* Kt   = sm + 8068;      // 2048
    float* Vt   = sm + 10116;     // 2048
    float* St   = sm + 12164;     // 8448
    float* rsum = sm + 20612;     // 128

    const int tid = threadIdx.x;
    const int m0  = blockIdx.x * 128;
    const int h   = blockIdx.y;
    const int b   = blockIdx.z;

    const float* QL = g_q + b * PB;
    const float* KL = g_k + b * PB;
    const float* VL = g_v + b * PB;
    float*       OL = g_o + b * PB;

    const float* rb = rel_bias + h * 3969;
    for (int i = tid; i < 3969; i += 256) relb[i] = rb[i];
    if (tid < 128) rsum[tid] = 0.0f;

    const int jblk = m0 >> 8;
    const int mc0  = m0 & 255;
    // Q tile: Qt[d][ml], 1024 float4s
#pragma unroll
    for (int it = 0; it < 4; it++) {
        const int i   = tid + it * 256;
        const int d   = i >> 5;
        const int off = (i & 31) * 4;
        *(float4*)&Qt[d * 128 + off] =
            *(const float4*)&QL[(h * 128 + 4 * d + jblk) * 256 + mc0 + off];
    }
    __syncthreads();

    // phase A thread map
    const int tx8 = (tid & 15) * 8;   // m columns tx8..tx8+7
    const int ty4 = (tid >> 4) * 4;   // n rows ty4..ty4+3 (within 64-tile)
    // phase B thread map (2-way n split)
    const int half = tid >> 7;
    const int t    = tid & 127;
    const int md8  = (t & 15) * 8;    // m columns md8..md8+7
    const int dg4  = (t >> 4) * 4;    // d rows dg4..dg4+3

    // bias column offsets for this thread's 8 query columns
    int Coff[8];
#pragma unroll
    for (int j = 0; j < 8; j++) {
        const int m = m0 + tx8 + j;
        Coff[j] = 1984 - (m >> 5) * 63 - (m & 31);
    }

    float cs[8] = {0.f, 0.f, 0.f, 0.f, 0.f, 0.f, 0.f, 0.f};
    ull o2[4][4];
#pragma unroll
    for (int r = 0; r < 4; r++)
#pragma unroll
        for (int p = 0; p < 4; p++) o2[r][p] = 0ull;

    for (int nt = 0; nt < 16; nt++) {
        const int n0   = nt * 64;
        const int iblk = n0 >> 8;
        const int nc0  = n0 & 255;
        // K,V tiles: 512 float4s each
#pragma unroll
        for (int it = 0; it < 2; it++) {
            const int i   = tid + it * 256;
            const int d   = i >> 4;
            const int off = (i & 15) * 4;
            const long ro = (long)(h * 128 + 4 * d + iblk) * 256 + nc0 + off;
            *(float4*)&Kt[d * 64 + off] = *(const float4*)&KL[ro];
            *(float4*)&Vt[d * 64 + off] = *(const float4*)&VL[ro];
        }
        __syncthreads();

        // ---- Phase A: S = K^T Q  (4n x 8m per thread) -----------------------
        ull s2[4][4];
#pragma unroll
        for (int i = 0; i < 4; i++)
#pragma unroll
            for (int p = 0; p < 4; p++) s2[i][p] = 0ull;

#pragma unroll 8
        for (int d = 0; d < 32; d++) {
            const float4 kv = *(const float4*)&Kt[d * 64 + ty4];
            ull q01, q23, q45, q67;
            lds_2u64(q01, q23, &Qt[d * 128 + tx8]);
            lds_2u64(q45, q67, &Qt[d * 128 + tx8 + 4]);
            const ull k0 = pack2(kv.x, kv.x);
            const ull k1 = pack2(kv.y, kv.y);
            const ull k2 = pack2(kv.z, kv.z);
            const ull k3 = pack2(kv.w, kv.w);
            s2[0][0] = ffma2(k0, q01, s2[0][0]); s2[0][1] = ffma2(k0, q23, s2[0][1]);
            s2[0][2] = ffma2(k0, q45, s2[0][2]); s2[0][3] = ffma2(k0, q67, s2[0][3]);
            s2[1][0] = ffma2(k1, q01, s2[1][0]); s2[1][1] = ffma2(k1, q23, s2[1][1]);
            s2[1][2] = ffma2(k1, q45, s2[1][2]); s2[1][3] = ffma2(k1, q67, s2[1][3]);
            s2[2][0] = ffma2(k2, q01, s2[2][0]); s2[2][1] = ffma2(k2, q23, s2[2][1]);
            s2[2][2] = ffma2(k2, q45, s2[2][2]); s2[2][3] = ffma2(k2, q67, s2[2][3]);
            s2[3][0] = ffma2(k3, q01, s2[3][0]); s2[3][1] = ffma2(k3, q23, s2[3][1]);
            s2[3][2] = ffma2(k3, q45, s2[3][2]); s2[3][3] = ffma2(k3, q67, s2[3][3]);
        }

        // bias + exp + store P + accumulate per-thread column sums
#pragma unroll
        for (int i = 0; i < 4; i++) {
            const int nl = ty4 + i;
            const int n  = n0 + nl;
            const int nb = (n >> 5) * 63 + (n & 31);
            float pv[8];
#pragma unroll
            for (int p = 0; p < 4; p++) {
                const float2 f = unpack2(s2[i][p]);
                pv[2 * p]     = __expf(fmaf(f.x, 0.0625f, relb[nb + Coff[2 * p]]));
                pv[2 * p + 1] = __expf(fmaf(f.y, 0.0625f, relb[nb + Coff[2 * p + 1]]));
            }
#pragma unroll
            for (int j = 0; j < 8; j++) cs[j] += pv[j];
            *(float4*)&St[nl * 132 + tx8]     = make_float4(pv[0], pv[1], pv[2], pv[3]);
            *(float4*)&St[nl * 132 + tx8 + 4] = make_float4(pv[4], pv[5], pv[6], pv[7]);
        }
        __syncthreads();

        // ---- Phase B: O[d][m] += V[d][n] * P[n][m]  (n-split halves) --------
#pragma unroll 4
        for (int nn = 0; nn < 32; nn++) {
            const int n = half * 32 + nn;
            const float v0 = Vt[(dg4 + 0) * 64 + n];
            const float v1 = Vt[(dg4 + 1) * 64 + n];
            const float v2 = Vt[(dg4 + 2) * 64 + n];
            const float v3 = Vt[(dg4 + 3) * 64 + n];
            ull p01, p23, p45, p67;
            lds_2u64(p01, p23, &St[n * 132 + md8]);
            lds_2u64(p45, p67, &St[n * 132 + md8 + 4]);
            const ull s0 = pack2(v0, v0);
            const ull s1 = pack2(v1, v1);
            const ull s2v = pack2(v2, v2);
            const ull s3 = pack2(v3, v3);
            o2[0][0] = ffma2(s0, p01, o2[0][0]); o2[0][1] = ffma2(s0, p23, o2[0][1]);
            o2[0][2] = ffma2(s0, p45, o2[0][2]); o2[0][3] = ffma2(s0, p67, o2[0][3]);
            o2[1][0] = ffma2(s1, p01, o2[1][0]); o2[1][1] = ffma2(s1, p23, o2[1][1]);
            o2[1][2] = ffma2(s1, p45, o2[1][2]); o2[1][3] = ffma2(s1, p67, o2[1][3]);
            o2[2][0] = ffma2(s2v, p01, o2[2][0]); o2[2][1] = ffma2(s2v, p23, o2[2][1]);
            o2[2][2] = ffma2(s2v, p45, o2[2][2]); o2[2][3] = ffma2(s2v, p67, o2[2][3]);
            o2[3][0] = ffma2(s3, p01, o2[3][0]); o2[3][1] = ffma2(s3, p23, o2[3][1]);
            o2[3][2] = ffma2(s3, p45, o2[3][2]); o2[3][3] = ffma2(s3, p67, o2[3][3]);
        }
        __syncthreads();
    }

    // softmax denominators: one atomic pass per thread
#pragma unroll
    for (int j = 0; j < 8; j++) atomicAdd(&rsum[tx8 + j], cs[j]);
    __syncthreads();

    if (tid < 128) {
        rsum[tid] = 1.0f / rsum[tid];
    } else {
        ull* stg = (ull*)St;
#pragma unroll
        for (int r = 0; r < 4; r++)
#pragma unroll
            for (int p = 0; p < 4; p++) stg[t * 16 + r * 4 + p] = o2[r][p];
    }
    __syncthreads();

    if (tid < 128) {
        ull* stg = (ull*)St;
#pragma unroll
        for (int r = 0; r < 4; r++)
#pragma unroll
            for (int p = 0; p < 4; p++)
                o2[r][p] = fadd2(o2[r][p], stg[t * 16 + r * 4 + p]);
        const float4 rv0 = *(const float4*)&rsum[md8];
        const float4 rv1 = *(const float4*)&rsum[md8 + 4];
#pragma unroll
        for (int r = 0; r < 4; r++) {
            const int d   = dg4 + r;
            const int row = h * 128 + 4 * d + jblk;
            const float2 f0 = unpack2(o2[r][0]);
            const float2 f1 = unpack2(o2[r][1]);
            const float2 f2 = unpack2(o2[r][2]);
            const float2 f3 = unpack2(o2[r][3]);
            const float4 w0 = make_float4(f0.x * rv0.x, f0.y * rv0.y, f1.x * rv0.z, f1.y * rv0.w);
            const float4 w1 = make_float4(f2.x * rv1.x, f2.y * rv1.y, f3.x * rv1.z, f3.y * rv1.w);
            *(float4*)&OL[row * 256 + mc0 + md8]     = w0;
            *(float4*)&OL[row * 256 + mc0 + md8 + 4] = w1;
        }
    }
}

// ------------------------------ Launch --------------------------------------
extern "C" void kernel_launch(void* const* d_in, const int* in_sizes, int n_in,
                              void* d_out, int out_size) {
    const float* x        = (const float*)d_in[0];
    const float* ln_g     = (const float*)d_in[1];
    const float* ln_b     = (const float*)d_in[2];
    const float* wq       = (const float*)d_in[3];
    const float* bq       = (const float*)d_in[4];
    const float* wk       = (const float*)d_in[5];
    const float* bk       = (const float*)d_in[6];
    const float* wv       = (const float*)d_in[7];
    const float* bv       = (const float*)d_in[8];
    const float* wo       = (const float*)d_in[9];
    const float* bo       = (const float*)d_in[10];
    const float* rel_bias = (const float*)d_in[11];
    float* out = (float*)d_out;
    (void)in_sizes; (void)n_in; (void)out_size;

    float *p_xn, *p_q, *p_k, *p_v, *p_o;
    cudaGetSymbolAddress((void**)&p_xn, g_xn);
    cudaGetSymbolAddress((void**)&p_q,  g_q);
    cudaGetSymbolAddress((void**)&p_k,  g_k);
    cudaGetSymbolAddress((void**)&p_v,  g_v);
    cudaGetSymbolAddress((void**)&p_o,  g_o);

    ln_kernel<<<dim3(4, BATCH), 256>>>(x, ln_g, ln_b);

    const dim3 ggrid(2, 8, BATCH);
    gemm_kernel<<<ggrid, 256>>>(p_xn, wq, bq, p_q, nullptr);
    gemm_kernel<<<ggrid, 256>>>(p_xn, wk, bk, p_k, nullptr);
    gemm_kernel<<<ggrid, 256>>>(p_xn, wv, bv, p_v, nullptr);

    const int smem_bytes = 20740 * (int)sizeof(float);  // 82960 B
    cudaFuncSetAttribute((const void*)attn_kernel,
                         cudaFuncAttributeMaxDynamicSharedMemorySize, smem_bytes);
    attn_kernel<<<dim3(8, 8, BATCH), 256, smem_bytes>>>(rel_bias);

    gemm_kernel<<<ggrid, 256>>>(p_o, wo, bo, out, x);
}

// round 11
// speedup vs baseline: 2.3527x; 2.2757x over previous
#include <cuda_runtime.h>
#include <cuda_bf16.h>

// ----------------------------------------------------------------------------
// RelativeAttention2d  (B=16, C=256, H=32 -> N=1024, HEADS=8, HS=32)
// Round: bf16 tensor-core (mma.sync m16n8k16) flash-style attention.
//   - softmax over keys == row-softmax of T = Q^T K  (standard FA layout)
//   - QKV GEMMs (fp32 SIMT) emit d-major bf16 [b][h][d][token] (coalesced)
//   - rel bias analytic: (yn-ym+31)*63 + (xn-xm+31), table in smem
//   - no max-subtract (logits bounded), fp32 exp + fp32 denominators
// ----------------------------------------------------------------------------

namespace {
constexpr int BATCH = 16;
constexpr int PB    = 256 * 1024;
}

typedef unsigned int u32;

__device__ float g_xn[BATCH * PB];
__device__ float g_o [BATCH * PB];
__device__ __nv_bfloat16 g_qb[BATCH * 8 * 32 * 1024];   // [b][h][d][m]
__device__ __nv_bfloat16 g_kb[BATCH * 8 * 32 * 1024];   // [b][h][d][n]
__device__ __nv_bfloat16 g_vb[BATCH * 8 * 32 * 1024];   // [b][h][d][n]

// ------------------------------- helpers ------------------------------------
__device__ __forceinline__ u32 bf2(float a, float b) {
    __nv_bfloat162 t = __floats2bfloat162_rn(a, b);   // .x=a (low), .y=b (high)
    return *(u32*)&t;
}
__device__ __forceinline__ u32 pk2(const __nv_bfloat16* lo, const __nv_bfloat16* hi) {
    return (u32)*(const unsigned short*)lo | ((u32)*(const unsigned short*)hi << 16);
}
__device__ __forceinline__ void mma_bf16(float& c0, float& c1, float& c2, float& c3,
                                         u32 a0, u32 a1, u32 a2, u32 a3,
                                         u32 b0, u32 b1) {
    asm volatile(
        "mma.sync.aligned.m16n8k16.row.col.f32.bf16.bf16.f32 "
        "{%0,%1,%2,%3}, {%4,%5,%6,%7}, {%8,%9}, {%0,%1,%2,%3};"
        : "+f"(c0), "+f"(c1), "+f"(c2), "+f"(c3)
        : "r"(a0), "r"(a1), "r"(a2), "r"(a3), "r"(b0), "r"(b1));
}

// ------------------------------ LayerNorm -----------------------------------
__global__ __launch_bounds__(256) void ln_kernel(const float* __restrict__ x,
                                                 const float* __restrict__ gamma,
                                                 const float* __restrict__ beta) {
    __shared__ float sg[256];
    __shared__ float sb[256];
    const int tid = threadIdx.x;
    sg[tid] = gamma[tid];
    sb[tid] = beta[tid];
    __syncthreads();

    const int b = blockIdx.y;
    const int p = blockIdx.x * 256 + tid;
    const float* xb = x + b * PB;

    float s = 0.f, ss = 0.f;
#pragma unroll 8
    for (int c = 0; c < 256; c++) {
        const float v = xb[c * 1024 + p];
        s += v;
        ss += v * v;
    }
    const float mu  = s * (1.0f / 256.0f);
    const float var = ss * (1.0f / 256.0f) - mu * mu;
    const float r   = rsqrtf(var + 1e-5f);

    float* ob = g_xn + b * PB;
#pragma unroll 8
    for (int c = 0; c < 256; c++) {
        const float v = xb[c * 1024 + p];
        ob[c * 1024 + p] = (v - mu) * r * sg[c] + sb[c];
    }
}

// ------------------------------ GEMM ----------------------------------------
// C[n][d] = sum_k A[n][k]*W[d][k] + bias[d].
// If Bf != null: write bf16 d-major [b][h][dh][token] (for Q/K/V).
// Else: write fp32 [n][d] (+ optional residual R) (for output projection).
__global__ __launch_bounds__(256, 2) void gemm_kernel(const float* __restrict__ Abase,
                                                      const float* __restrict__ W,
                                                      const float* __restrict__ bias,
                                                      float* __restrict__ Cbase,
                                                      __nv_bfloat16* __restrict__ Bf,
                                                      const float* __restrict__ Rbase) {
    __shared__ float As[16][132];
    __shared__ float Bs[16][132];

    const int b   = blockIdx.z;
    const float* A = Abase + b * PB;
    const int n0  = blockIdx.y * 128;
    const int d0  = blockIdx.x * 128;
    const int tid = threadIdx.x;
    const int tx8 = (tid & 15) * 8;
    const int ty8 = (tid >> 4) * 8;
    const int lr  = tid >> 1;
    const int lc  = (tid & 1) * 8;

    float acc[8][8];
#pragma unroll
    for (int i = 0; i < 8; i++)
#pragma unroll
        for (int j = 0; j < 8; j++) acc[i][j] = 0.f;

    for (int k0 = 0; k0 < 256; k0 += 16) {
        const float4 a0 = *(const float4*)&A[(n0 + lr) * 256 + k0 + lc];
        const float4 a1 = *(const float4*)&A[(n0 + lr) * 256 + k0 + lc + 4];
        const float4 b0 = *(const float4*)&W[(d0 + lr) * 256 + k0 + lc];
        const float4 b1 = *(const float4*)&W[(d0 + lr) * 256 + k0 + lc + 4];
        As[lc + 0][lr] = a0.x; As[lc + 1][lr] = a0.y; As[lc + 2][lr] = a0.z; As[lc + 3][lr] = a0.w;
        As[lc + 4][lr] = a1.x; As[lc + 5][lr] = a1.y; As[lc + 6][lr] = a1.z; As[lc + 7][lr] = a1.w;
        Bs[lc + 0][lr] = b0.x; Bs[lc + 1][lr] = b0.y; Bs[lc + 2][lr] = b0.z; Bs[lc + 3][lr] = b0.w;
        Bs[lc + 4][lr] = b1.x; Bs[lc + 5][lr] = b1.y; Bs[lc + 6][lr] = b1.z; Bs[lc + 7][lr] = b1.w;
        __syncthreads();

#pragma unroll
        for (int kk = 0; kk < 16; kk++) {
            const float4 av0 = *(const float4*)&As[kk][ty8];
            const float4 av1 = *(const float4*)&As[kk][ty8 + 4];
            const float4 bv0 = *(const float4*)&Bs[kk][tx8];
            const float4 bv1 = *(const float4*)&Bs[kk][tx8 + 4];
            const float ar[8] = {av0.x, av0.y, av0.z, av0.w, av1.x, av1.y, av1.z, av1.w};
            const float br[8] = {bv0.x, bv0.y, bv0.z, bv0.w, bv1.x, bv1.y, bv1.z, bv1.w};
#pragma unroll
            for (int i = 0; i < 8; i++)
#pragma unroll
                for (int j = 0; j < 8; j++)
                    acc[i][j] = fmaf(ar[i], br[j], acc[i][j]);
        }
        __syncthreads();
    }

    const int col = d0 + tx8;
    const float4 bi0 = *(const float4*)&bias[col];
    const float4 bi1 = *(const float4*)&bias[col + 4];
#pragma unroll
    for (int i = 0; i < 8; i++) {
        const int row = n0 + ty8 + i;
        float w[8];
        w[0] = acc[i][0] + bi0.x; w[1] = acc[i][1] + bi0.y;
        w[2] = acc[i][2] + bi0.z; w[3] = acc[i][3] + bi0.w;
        w[4] = acc[i][4] + bi1.x; w[5] = acc[i][5] + bi1.y;
        w[6] = acc[i][6] + bi1.z; w[7] = acc[i][7] + bi1.w;
        if (Bf != nullptr) {
            // flat-view decode: row = h*128 + 4*dh + jblk, token m = jblk*256 + col
            const int h  = row >> 7;
            const int rr = row & 127;
            const int dh = rr >> 2;
            const int m  = (rr & 3) * 256 + col;
            uint4 st;
            st.x = bf2(w[0], w[1]); st.y = bf2(w[2], w[3]);
            st.z = bf2(w[4], w[5]); st.w = bf2(w[6], w[7]);
            *(uint4*)&Bf[((size_t)((b * 8 + h) * 32 + dh)) * 1024 + m] = st;
        } else {
            float4 w0 = make_float4(w[0], w[1], w[2], w[3]);
            float4 w1 = make_float4(w[4], w[5], w[6], w[7]);
            if (Rbase != nullptr) {
                const float4 r0 = *(const float4*)&Rbase[b * PB + row * 256 + col];
                const float4 r1 = *(const float4*)&Rbase[b * PB + row * 256 + col + 4];
                w0.x += r0.x; w0.y += r0.y; w0.z += r0.z; w0.w += r0.w;
                w1.x += r1.x; w1.y += r1.y; w1.z += r1.z; w1.w += r1.w;
            }
            *(float4*)&Cbase[b * PB + row * 256 + col]     = w0;
            *(float4*)&Cbase[b * PB + row * 256 + col + 4] = w1;
        }
    }
}

// ------------------------------ Attention (bf16 HMMA) ------------------------
// CTA = (128-query tile, head, batch); 8 warps x 16 query rows each.
// Loop over 16 key tiles of 64.  S = Q^T K (frag-level), P = exp(S/16 + bias),
// O += P V; final O /= rowsum.  All frags per PTX m16n8k16 layouts.
__global__ __launch_bounds__(256) void attn_kernel(const float* __restrict__ rel_bias) {
    __shared__ __align__(16) float relb[3972];
    __shared__ __align__(16) __nv_bfloat16 Qs[32 * 128];  // [d][m], stride 128
    __shared__ __align__(16) __nv_bfloat16 Ks[32 * 72];   // [d][n], stride 72
    __shared__ __align__(16) __nv_bfloat16 Vs[32 * 72];   // [d][n], stride 72

    const int tid  = threadIdx.x;
    const int w    = tid >> 5;
    const int lane = tid & 31;
    const int g    = lane >> 2;     // groupID (fragment row)
    const int tg   = lane & 3;      // threadID in group

    const int m0 = blockIdx.x * 128;
    const int h  = blockIdx.y;
    const int b  = blockIdx.z;
    const int bh = b * 8 + h;

    const __nv_bfloat16* qh = g_qb + (size_t)bh * 32768;
    const __nv_bfloat16* kh = g_kb + (size_t)bh * 32768;
    const __nv_bfloat16* vh = g_vb + (size_t)bh * 32768;

    // rel-bias table
    const float* rb = rel_bias + h * 3969;
    for (int i = tid; i < 3969; i += 256) relb[i] = rb[i];

    // Q tile [d][m] cooperative coalesced load (32 rows x 256B)
    {
        const int d    = tid >> 3;
        const int moff = (tid & 7) * 16;
        const uint4* src = (const uint4*)(qh + (size_t)d * 1024 + m0 + moff);
        *(uint4*)(Qs + d * 128 + moff)     = src[0];
        *(uint4*)(Qs + d * 128 + moff + 8) = src[1];
    }
    __syncthreads();

    // Q A-fragments (per-lane u16 gathers; once per CTA)
    const int mloc_lo = w * 16 + g;
    const int mloc_hi = mloc_lo + 8;
    u32 qa[2][4];
#pragma unroll
    for (int kc = 0; kc < 2; kc++) {
        const int k0 = kc * 16 + tg * 2;
        qa[kc][0] = pk2(&Qs[(k0 + 0) * 128 + mloc_lo], &Qs[(k0 + 1) * 128 + mloc_lo]);
        qa[kc][1] = pk2(&Qs[(k0 + 0) * 128 + mloc_hi], &Qs[(k0 + 1) * 128 + mloc_hi]);
        qa[kc][2] = pk2(&Qs[(k0 + 8) * 128 + mloc_lo], &Qs[(k0 + 9) * 128 + mloc_lo]);
        qa[kc][3] = pk2(&Qs[(k0 + 8) * 128 + mloc_hi], &Qs[(k0 + 9) * 128 + mloc_hi]);
    }

    const int m_lo = m0 + mloc_lo;
    const int m_hi = m_lo + 8;
    const int Clo  = 1984 - (m_lo >> 5) * 63 - (m_lo & 31);  // + yn*63+xn = bias idx
    const int Chi  = 1984 - (m_hi >> 5) * 63 - (m_hi & 31);

    float oc[4][4];
#pragma unroll
    for (int df = 0; df < 4; df++)
#pragma unroll
        for (int r = 0; r < 4; r++) oc[df][r] = 0.f;
    float rs_lo = 0.f, rs_hi = 0.f;

    const int ld   = tid >> 3;           // tile-load row
    const int noff = (tid & 7) * 8;      // tile-load col offset

    for (int nt = 0; nt < 16; nt++) {
        const int n0 = nt * 64;
        __syncthreads();
        *(uint4*)(Ks + ld * 72 + noff) = *(const uint4*)(kh + (size_t)ld * 1024 + n0 + noff);
        *(uint4*)(Vs + ld * 72 + noff) = *(const uint4*)(vh + (size_t)ld * 1024 + n0 + noff);
        __syncthreads();

        u32 pa[4][4];
#pragma unroll
        for (int nf = 0; nf < 8; nf++) {
            float c0 = 0.f, c1 = 0.f, c2 = 0.f, c3 = 0.f;
            const int nb = nf * 8 + g;   // B-frag column (key within tile)
#pragma unroll
            for (int kc = 0; kc < 2; kc++) {
                const int d0 = kc * 16 + tg * 2;
                const u32 b0 = pk2(&Ks[(d0 + 0) * 72 + nb], &Ks[(d0 + 1) * 72 + nb]);
                const u32 b1 = pk2(&Ks[(d0 + 8) * 72 + nb], &Ks[(d0 + 9) * 72 + nb]);
                mma_bf16(c0, c1, c2, c3, qa[kc][0], qa[kc][1], qa[kc][2], qa[kc][3], b0, b1);
            }
            // epilogue: bias + exp (fp32), accumulate denominators
            const int n1 = n0 + nf * 8 + tg * 2;
            const int n2 = n1 + 1;
            const int i1 = (n1 >> 5) * 63 + (n1 & 31);
            const int i2 = (n2 >> 5) * 63 + (n2 & 31);
            const float p0 = __expf(fmaf(c0, 0.0625f, relb[i1 + Clo]));
            const float p1 = __expf(fmaf(c1, 0.0625f, relb[i2 + Clo]));
            const float p2 = __expf(fmaf(c2, 0.0625f, relb[i1 + Chi]));
            const float p3 = __expf(fmaf(c3, 0.0625f, relb[i2 + Chi]));
            rs_lo += p0 + p1;
            rs_hi += p2 + p3;
            const int f = nf >> 1;
            if ((nf & 1) == 0) {
                pa[f][0] = bf2(p0, p1);
                pa[f][1] = bf2(p2, p3);
            } else {
                pa[f][2] = bf2(p0, p1);
                pa[f][3] = bf2(p2, p3);
            }
        }

        // O += P V    (A = P frags, B = V from d-major smem, pairs along n)
#pragma unroll
        for (int f = 0; f < 4; f++) {
#pragma unroll
            for (int df = 0; df < 4; df++) {
                const __nv_bfloat16* vp = &Vs[(df * 8 + g) * 72 + f * 16 + tg * 2];
                const u32 b0 = *(const u32*)(vp);
                const u32 b1 = *(const u32*)(vp + 8);
                mma_bf16(oc[df][0], oc[df][1], oc[df][2], oc[df][3],
                         pa[f][0], pa[f][1], pa[f][2], pa[f][3], b0, b1);
            }
        }
    }

    // reduce row sums across the 4 lanes sharing each row
    rs_lo += __shfl_xor_sync(0xffffffffu, rs_lo, 1);
    rs_lo += __shfl_xor_sync(0xffffffffu, rs_lo, 2);
    rs_hi += __shfl_xor_sync(0xffffffffu, rs_hi, 1);
    rs_hi += __shfl_xor_sync(0xffffffffu, rs_hi, 2);
    const float inv_lo = 1.0f / rs_lo;
    const float inv_hi = 1.0f / rs_hi;

    // write O to fp32 flat layout (32B-sector-coalesced across lanes)
    float* OL = g_o + b * PB;
    const int jblk = m0 >> 8;
    const int mclo = m_lo & 255;
    const int mchi = m_hi & 255;
#pragma unroll
    for (int df = 0; df < 4; df++) {
        const int d1 = df * 8 + tg * 2;
        const int d2 = d1 + 1;
        const int r1 = h * 128 + 4 * d1 + jblk;
        const int r2 = h * 128 + 4 * d2 + jblk;
        OL[r1 * 256 + mclo] = oc[df][0] * inv_lo;
        OL[r2 * 256 + mclo] = oc[df][1] * inv_lo;
        OL[r1 * 256 + mchi] = oc[df][2] * inv_hi;
        OL[r2 * 256 + mchi] = oc[df][3] * inv_hi;
    }
}

// ------------------------------ Launch --------------------------------------
extern "C" void kernel_launch(void* const* d_in, const int* in_sizes, int n_in,
                              void* d_out, int out_size) {
    const float* x        = (const float*)d_in[0];
    const float* ln_g     = (const float*)d_in[1];
    const float* ln_b     = (const float*)d_in[2];
    const float* wq       = (const float*)d_in[3];
    const float* bq       = (const float*)d_in[4];
    const float* wk       = (const float*)d_in[5];
    const float* bk       = (const float*)d_in[6];
    const float* wv       = (const float*)d_in[7];
    const float* bv       = (const float*)d_in[8];
    const float* wo       = (const float*)d_in[9];
    const float* bo       = (const float*)d_in[10];
    const float* rel_bias = (const float*)d_in[11];
    float* out = (float*)d_out;
    (void)in_sizes; (void)n_in; (void)out_size;

    float *p_xn, *p_o;
    __nv_bfloat16 *p_qb, *p_kb, *p_vb;
    cudaGetSymbolAddress((void**)&p_xn, g_xn);
    cudaGetSymbolAddress((void**)&p_o,  g_o);
    cudaGetSymbolAddress((void**)&p_qb, g_qb);
    cudaGetSymbolAddress((void**)&p_kb, g_kb);
    cudaGetSymbolAddress((void**)&p_vb, g_vb);

    ln_kernel<<<dim3(4, BATCH), 256>>>(x, ln_g, ln_b);

    const dim3 ggrid(2, 8, BATCH);
    gemm_kernel<<<ggrid, 256>>>(p_xn, wq, bq, nullptr, p_qb, nullptr);
    gemm_kernel<<<ggrid, 256>>>(p_xn, wk, bk, nullptr, p_kb, nullptr);
    gemm_kernel<<<ggrid, 256>>>(p_xn, wv, bv, nullptr, p_vb, nullptr);

    attn_kernel<<<dim3(8, 8, BATCH), 256>>>(rel_bias);

    gemm_kernel<<<ggrid, 256>>>(p_o, wo, bo, out, nullptr, x);
}

// round 12
// speedup vs baseline: 4.6476x; 1.9754x over previous
#include <cuda_runtime.h>
#include <cuda_bf16.h>

// ----------------------------------------------------------------------------
// RelativeAttention2d  (B=16, C=256, H=32 -> N=1024, HEADS=8, HS=32)
// Round: everything on bf16 tensor cores (mma.sync m16n8k16).
//   - LayerNorm emits bf16 xn  [16384][256] flat view
//   - 4 GEMMs: cp.async double-buffered, ldmatrix-fed HMMA, fp32 accum
//       QKV mode: epilogue scatters bf16 into d-major [b][h][d][token]
//       final mode: epilogue adds bias + fp32 residual, writes fp32 out
//   - attention: bf16 HMMA flash-style (row-softmax of Q^T K), bf16 O out
//   - rel bias analytic: (yn-ym+31)*63 + (xn-xm+31); no max-subtract
// ----------------------------------------------------------------------------

namespace {
constexpr int BATCH = 16;
constexpr int PB    = 256 * 1024;
}

typedef unsigned int u32;

__device__ __nv_bfloat16 g_xnb[BATCH * PB];             // LN out, [16384][256]
__device__ __nv_bfloat16 g_ob [BATCH * PB];             // attn out, [16384][256]
__device__ __nv_bfloat16 g_qb[BATCH * 8 * 32 * 1024];   // [b][h][d][m]
__device__ __nv_bfloat16 g_kb[BATCH * 8 * 32 * 1024];
__device__ __nv_bfloat16 g_vb[BATCH * 8 * 32 * 1024];
__device__ __nv_bfloat16 g_wb[4 * 256 * 256];           // bf16 weights q,k,v,o

// ------------------------------- helpers ------------------------------------
__device__ __forceinline__ u32 bf2(float a, float b) {
    __nv_bfloat162 t = __floats2bfloat162_rn(a, b);
    return *(u32*)&t;
}
__device__ __forceinline__ u32 pk2(const __nv_bfloat16* lo, const __nv_bfloat16* hi) {
    return (u32)*(const unsigned short*)lo | ((u32)*(const unsigned short*)hi << 16);
}
__device__ __forceinline__ void mma_bf16(float& c0, float& c1, float& c2, float& c3,
                                         u32 a0, u32 a1, u32 a2, u32 a3,
                                         u32 b0, u32 b1) {
    asm volatile(
        "mma.sync.aligned.m16n8k16.row.col.f32.bf16.bf16.f32 "
        "{%0,%1,%2,%3}, {%4,%5,%6,%7}, {%8,%9}, {%0,%1,%2,%3};"
        : "+f"(c0), "+f"(c1), "+f"(c2), "+f"(c3)
        : "r"(a0), "r"(a1), "r"(a2), "r"(a3), "r"(b0), "r"(b1));
}
__device__ __forceinline__ void ldsm4(u32& r0, u32& r1, u32& r2, u32& r3,
                                      const __nv_bfloat16* p) {
    u32 a = (u32)__cvta_generic_to_shared(p);
    asm volatile("ldmatrix.sync.aligned.m8n8.x4.shared.b16 {%0,%1,%2,%3}, [%4];"
                 : "=r"(r0), "=r"(r1), "=r"(r2), "=r"(r3) : "r"(a));
}
__device__ __forceinline__ void cp16(u32 dst, const void* src) {
    asm volatile("cp.async.cg.shared.global [%0], [%1], 16;" :: "r"(dst), "l"(src));
}

// ------------------------------ LayerNorm (-> bf16) --------------------------
__global__ __launch_bounds__(256) void ln_kernel(const float* __restrict__ x,
                                                 const float* __restrict__ gamma,
                                                 const float* __restrict__ beta) {
    __shared__ float sg[256];
    __shared__ float sb[256];
    const int tid = threadIdx.x;
    sg[tid] = gamma[tid];
    sb[tid] = beta[tid];
    __syncthreads();

    const int b = blockIdx.y;
    const int p = blockIdx.x * 256 + tid;
    const float* xb = x + b * PB;

    float s = 0.f, ss = 0.f;
#pragma unroll 8
    for (int c = 0; c < 256; c++) {
        const float v = xb[c * 1024 + p];
        s += v;
        ss += v * v;
    }
    const float mu  = s * (1.0f / 256.0f);
    const float var = ss * (1.0f / 256.0f) - mu * mu;
    const float r   = rsqrtf(var + 1e-5f);

    __nv_bfloat16* ob = g_xnb + (size_t)b * PB;
#pragma unroll 8
    for (int c = 0; c < 256; c++) {
        const float v = xb[c * 1024 + p];
        ob[c * 1024 + p] = __float2bfloat16((v - mu) * r * sg[c] + sb[c]);
    }
}

// --------------------- weight fp32 -> bf16 converter -------------------------
__global__ __launch_bounds__(256) void cvt_kernel(const float* __restrict__ w0,
                                                  const float* __restrict__ w1,
                                                  const float* __restrict__ w2,
                                                  const float* __restrict__ w3) {
    const float* src = (blockIdx.y == 0) ? w0 : (blockIdx.y == 1) ? w1
                     : (blockIdx.y == 2) ? w2 : w3;
    __nv_bfloat16* dst = g_wb + (size_t)blockIdx.y * 65536;
    const int i = (blockIdx.x * 256 + threadIdx.x) * 4;
    const float4 v = *(const float4*)&src[i];
    uint2 st;
    st.x = bf2(v.x, v.y);
    st.y = bf2(v.z, v.w);
    *(uint2*)&dst[i] = st;
}

// ------------------------- bf16 HMMA GEMM ------------------------------------
// C[R][col] = sum_k A[R][k] * W[col][k]   (R = 0..16383 tokens, col = 0..255)
// CTA tile 128x128, 8 warps (4M x 2N), k-slices of 16, cp.async double buffer.
// outQ mode: bf16 head-layout scatter; outF mode: fp32 + bias + residual.
__device__ __forceinline__ void stq(__nv_bfloat16* dst, int R, int col,
                                    float v0, float v1) {
    const int b  = R >> 10, r = R & 1023;
    const int h  = r >> 7;
    const int dh = (r >> 2) & 31;
    const int jb = r & 3;
    const size_t off = ((size_t)((b * 8 + h) * 32 + dh) << 10) + (jb * 256 + col);
    *(u32*)&dst[off] = bf2(v0, v1);
}

__global__ __launch_bounds__(256, 2) void gemm_bf16_kernel(
    const __nv_bfloat16* __restrict__ A,    // [16384][256]
    const __nv_bfloat16* __restrict__ Wb,   // [256][256]
    const float* __restrict__ bias,
    __nv_bfloat16* __restrict__ outQ,       // QKV mode (or null)
    float* __restrict__ outF,               // final mode (or null)
    const float* __restrict__ Res)          // residual for final mode
{
    __shared__ __align__(16) __nv_bfloat16 As[2][3072];   // [128][24] per buf
    __shared__ __align__(16) __nv_bfloat16 Bs[2][3072];

    const int tid  = threadIdx.x;
    const int lane = tid & 31;
    const int w    = tid >> 5;
    const int g    = lane >> 2;
    const int tg   = lane & 3;
    const int bn   = blockIdx.x;
    const int bm   = blockIdx.y;
    const int warpM = (w & 3) * 32;
    const int warpN = (w >> 2) * 64;

    const int lrow  = tid >> 1;
    const int lhalf = (tid & 1) * 8;
    const __nv_bfloat16* Ag = A  + (size_t)(bm * 128 + lrow) * 256 + lhalf;
    const __nv_bfloat16* Bg = Wb + (size_t)(bn * 128 + lrow) * 256 + lhalf;
    const u32 sA = (u32)__cvta_generic_to_shared(&As[0][lrow * 24 + lhalf]);
    const u32 sB = (u32)__cvta_generic_to_shared(&Bs[0][lrow * 24 + lhalf]);

    float acc[2][8][4];
#pragma unroll
    for (int i = 0; i < 2; i++)
#pragma unroll
        for (int j = 0; j < 8; j++)
#pragma unroll
            for (int r = 0; r < 4; r++) acc[i][j][r] = 0.f;

    cp16(sA, Ag);
    cp16(sB, Bg);
    asm volatile("cp.async.commit_group;");

    const int aRow = lane & 15;
    const int aCol = (lane >> 4) * 8;
    const int bRow = ((lane >> 4) << 3) + (lane & 7);
    const int bCol = ((lane >> 3) & 1) * 8;

    for (int ks = 0; ks < 16; ks++) {
        const int buf = ks & 1;
        if (ks < 15) {
            cp16(sA + (buf ^ 1) * 6144, Ag + (ks + 1) * 16);
            cp16(sB + (buf ^ 1) * 6144, Bg + (ks + 1) * 16);
            asm volatile("cp.async.commit_group;");
            asm volatile("cp.async.wait_group 1;");
        } else {
            asm volatile("cp.async.wait_group 0;");
        }
        __syncthreads();

        const __nv_bfloat16* sa = As[buf];
        const __nv_bfloat16* sb = Bs[buf];
        u32 a0[4], a1[4];
        ldsm4(a0[0], a0[1], a0[2], a0[3], sa + (warpM + aRow) * 24 + aCol);
        ldsm4(a1[0], a1[1], a1[2], a1[3], sa + (warpM + 16 + aRow) * 24 + aCol);
#pragma unroll
        for (int nf16 = 0; nf16 < 4; nf16++) {
            u32 b0, b1, b2, b3;
            ldsm4(b0, b1, b2, b3, sb + (warpN + nf16 * 16 + bRow) * 24 + bCol);
            float* cl0 = acc[0][nf16 * 2];
            float* ch0 = acc[0][nf16 * 2 + 1];
            float* cl1 = acc[1][nf16 * 2];
            float* ch1 = acc[1][nf16 * 2 + 1];
            mma_bf16(cl0[0], cl0[1], cl0[2], cl0[3], a0[0], a0[1], a0[2], a0[3], b0, b1);
            mma_bf16(ch0[0], ch0[1], ch0[2], ch0[3], a0[0], a0[1], a0[2], a0[3], b2, b3);
            mma_bf16(cl1[0], cl1[1], cl1[2], cl1[3], a1[0], a1[1], a1[2], a1[3], b0, b1);
            mma_bf16(ch1[0], ch1[1], ch1[2], ch1[3], a1[0], a1[1], a1[2], a1[3], b2, b3);
        }
        __syncthreads();
    }

    // epilogue
#pragma unroll
    for (int mi = 0; mi < 2; mi++) {
        const int R0 = bm * 128 + warpM + mi * 16 + g;
#pragma unroll
        for (int nf = 0; nf < 8; nf++) {
            const int col = bn * 128 + warpN + nf * 8 + 2 * tg;
            const float2 bv = *(const float2*)&bias[col];
            const float v0 = acc[mi][nf][0] + bv.x;
            const float v1 = acc[mi][nf][1] + bv.y;
            const float v2 = acc[mi][nf][2] + bv.x;
            const float v3 = acc[mi][nf][3] + bv.y;
            if (outQ != nullptr) {
                stq(outQ, R0,     col, v0, v1);
                stq(outQ, R0 + 8, col, v2, v3);
            } else {
                const size_t i0 = (size_t)R0 * 256 + col;
                const size_t i1 = i0 + 8 * 256;
                const float2 r0 = *(const float2*)&Res[i0];
                const float2 r1 = *(const float2*)&Res[i1];
                *(float2*)&outF[i0] = make_float2(v0 + r0.x, v1 + r0.y);
                *(float2*)&outF[i1] = make_float2(v2 + r1.x, v3 + r1.y);
            }
        }
    }
}

// ------------------------------ Attention (bf16 HMMA) ------------------------
__global__ __launch_bounds__(256) void attn_kernel(const float* __restrict__ rel_bias) {
    __shared__ __align__(16) float relb[3972];
    __shared__ __align__(16) __nv_bfloat16 Qs[32 * 128];
    __shared__ __align__(16) __nv_bfloat16 Ks[32 * 72];
    __shared__ __align__(16) __nv_bfloat16 Vs[32 * 72];

    const int tid  = threadIdx.x;
    const int w    = tid >> 5;
    const int lane = tid & 31;
    const int g    = lane >> 2;
    const int tg   = lane & 3;

    const int m0 = blockIdx.x * 128;
    const int h  = blockIdx.y;
    const int b  = blockIdx.z;
    const int bh = b * 8 + h;

    const __nv_bfloat16* qh = g_qb + (size_t)bh * 32768;
    const __nv_bfloat16* kh = g_kb + (size_t)bh * 32768;
    const __nv_bfloat16* vh = g_vb + (size_t)bh * 32768;

    const float* rb = rel_bias + h * 3969;
    for (int i = tid; i < 3969; i += 256) relb[i] = rb[i];

    {
        const int d    = tid >> 3;
        const int moff = (tid & 7) * 16;
        const uint4* src = (const uint4*)(qh + (size_t)d * 1024 + m0 + moff);
        *(uint4*)(Qs + d * 128 + moff)     = src[0];
        *(uint4*)(Qs + d * 128 + moff + 8) = src[1];
    }
    __syncthreads();

    const int mloc_lo = w * 16 + g;
    const int mloc_hi = mloc_lo + 8;
    u32 qa[2][4];
#pragma unroll
    for (int kc = 0; kc < 2; kc++) {
        const int k0 = kc * 16 + tg * 2;
        qa[kc][0] = pk2(&Qs[(k0 + 0) * 128 + mloc_lo], &Qs[(k0 + 1) * 128 + mloc_lo]);
        qa[kc][1] = pk2(&Qs[(k0 + 0) * 128 + mloc_hi], &Qs[(k0 + 1) * 128 + mloc_hi]);
        qa[kc][2] = pk2(&Qs[(k0 + 8) * 128 + mloc_lo], &Qs[(k0 + 9) * 128 + mloc_lo]);
        qa[kc][3] = pk2(&Qs[(k0 + 8) * 128 + mloc_hi], &Qs[(k0 + 9) * 128 + mloc_hi]);
    }

    const int m_lo = m0 + mloc_lo;
    const int m_hi = m_lo + 8;
    const int Clo  = 1984 - (m_lo >> 5) * 63 - (m_lo & 31);
    const int Chi  = 1984 - (m_hi >> 5) * 63 - (m_hi & 31);

    float oc[4][4];
#pragma unroll
    for (int df = 0; df < 4; df++)
#pragma unroll
        for (int r = 0; r < 4; r++) oc[df][r] = 0.f;
    float rs_lo = 0.f, rs_hi = 0.f;

    const int ld   = tid >> 3;
    const int noff = (tid & 7) * 8;

    for (int nt = 0; nt < 16; nt++) {
        const int n0 = nt * 64;
        __syncthreads();
        *(uint4*)(Ks + ld * 72 + noff) = *(const uint4*)(kh + (size_t)ld * 1024 + n0 + noff);
        *(uint4*)(Vs + ld * 72 + noff) = *(const uint4*)(vh + (size_t)ld * 1024 + n0 + noff);
        __syncthreads();

        u32 pa[4][4];
#pragma unroll
        for (int nf = 0; nf < 8; nf++) {
            float c0 = 0.f, c1 = 0.f, c2 = 0.f, c3 = 0.f;
            const int nb = nf * 8 + g;
#pragma unroll
            for (int kc = 0; kc < 2; kc++) {
                const int d0 = kc * 16 + tg * 2;
                const u32 b0 = pk2(&Ks[(d0 + 0) * 72 + nb], &Ks[(d0 + 1) * 72 + nb]);
                const u32 b1 = pk2(&Ks[(d0 + 8) * 72 + nb], &Ks[(d0 + 9) * 72 + nb]);
                mma_bf16(c0, c1, c2, c3, qa[kc][0], qa[kc][1], qa[kc][2], qa[kc][3], b0, b1);
            }
            const int n1 = n0 + nf * 8 + tg * 2;
            const int n2 = n1 + 1;
            const int i1 = (n1 >> 5) * 63 + (n1 & 31);
            const int i2 = (n2 >> 5) * 63 + (n2 & 31);
            const float p0 = __expf(fmaf(c0, 0.0625f, relb[i1 + Clo]));
            const float p1 = __expf(fmaf(c1, 0.0625f, relb[i2 + Clo]));
            const float p2 = __expf(fmaf(c2, 0.0625f, relb[i1 + Chi]));
            const float p3 = __expf(fmaf(c3, 0.0625f, relb[i2 + Chi]));
            rs_lo += p0 + p1;
            rs_hi += p2 + p3;
            const int f = nf >> 1;
            if ((nf & 1) == 0) {
                pa[f][0] = bf2(p0, p1);
                pa[f][1] = bf2(p2, p3);
            } else {
                pa[f][2] = bf2(p0, p1);
                pa[f][3] = bf2(p2, p3);
            }
        }

#pragma unroll
        for (int f = 0; f < 4; f++) {
#pragma unroll
            for (int df = 0; df < 4; df++) {
                const __nv_bfloat16* vp = &Vs[(df * 8 + g) * 72 + f * 16 + tg * 2];
                const u32 b0 = *(const u32*)(vp);
                const u32 b1 = *(const u32*)(vp + 8);
                mma_bf16(oc[df][0], oc[df][1], oc[df][2], oc[df][3],
                         pa[f][0], pa[f][1], pa[f][2], pa[f][3], b0, b1);
            }
        }
    }

    rs_lo += __shfl_xor_sync(0xffffffffu, rs_lo, 1);
    rs_lo += __shfl_xor_sync(0xffffffffu, rs_lo, 2);
    rs_hi += __shfl_xor_sync(0xffffffffu, rs_hi, 1);
    rs_hi += __shfl_xor_sync(0xffffffffu, rs_hi, 2);
    const float inv_lo = 1.0f / rs_lo;
    const float inv_hi = 1.0f / rs_hi;

    __nv_bfloat16* OL = g_ob + (size_t)b * PB;
    const int jblk = m0 >> 8;
    const int mclo = m_lo & 255;
    const int mchi = m_hi & 255;
#pragma unroll
    for (int df = 0; df < 4; df++) {
        const int d1 = df * 8 + tg * 2;
        const int d2 = d1 + 1;
        const int r1 = h * 128 + 4 * d1 + jblk;
        const int r2 = h * 128 + 4 * d2 + jblk;
        OL[r1 * 256 + mclo] = __float2bfloat16(oc[df][0] * inv_lo);
        OL[r2 * 256 + mclo] = __float2bfloat16(oc[df][1] * inv_lo);
        OL[r1 * 256 + mchi] = __float2bfloat16(oc[df][2] * inv_hi);
        OL[r2 * 256 + mchi] = __float2bfloat16(oc[df][3] * inv_hi);
    }
}

// ------------------------------ Launch --------------------------------------
extern "C" void kernel_launch(void* const* d_in, const int* in_sizes, int n_in,
                              void* d_out, int out_size) {
    const float* x        = (const float*)d_in[0];
    const float* ln_g     = (const float*)d_in[1];
    const float* ln_b     = (const float*)d_in[2];
    const float* wq       = (const float*)d_in[3];
    const float* bq       = (const float*)d_in[4];
    const float* wk       = (const float*)d_in[5];
    const float* bk       = (const float*)d_in[6];
    const float* wv       = (const float*)d_in[7];
    const float* bv       = (const float*)d_in[8];
    const float* wo       = (const float*)d_in[9];
    const float* bo       = (const float*)d_in[10];
    const float* rel_bias = (const float*)d_in[11];
    float* out = (float*)d_out;
    (void)in_sizes; (void)n_in; (void)out_size;

    __nv_bfloat16 *p_xnb, *p_ob, *p_qb, *p_kb, *p_vb, *p_wb;
    cudaGetSymbolAddress((void**)&p_xnb, g_xnb);
    cudaGetSymbolAddress((void**)&p_ob,  g_ob);
    cudaGetSymbolAddress((void**)&p_qb,  g_qb);
    cudaGetSymbolAddress((void**)&p_kb,  g_kb);
    cudaGetSymbolAddress((void**)&p_vb,  g_vb);
    cudaGetSymbolAddress((void**)&p_wb,  g_wb);

    ln_kernel<<<dim3(4, BATCH), 256>>>(x, ln_g, ln_b);
    cvt_kernel<<<dim3(64, 4), 256>>>(wq, wk, wv, wo);

    const dim3 ggrid(2, 128);
    gemm_bf16_kernel<<<ggrid, 256>>>(p_xnb, p_wb,             bq, p_qb, nullptr, nullptr);
    gemm_bf16_kernel<<<ggrid, 256>>>(p_xnb, p_wb + 1 * 65536, bk, p_kb, nullptr, nullptr);
    gemm_bf16_kernel<<<ggrid, 256>>>(p_xnb, p_wb + 2 * 65536, bv, p_vb, nullptr, nullptr);

    attn_kernel<<<dim3(8, 8, BATCH), 256>>>(rel_bias);

    gemm_bf16_kernel<<<ggrid, 256>>>(p_ob, p_wb + 3 * 65536, bo, nullptr, out, x);
}

// round 14
// speedup vs baseline: 5.7262x; 1.2321x over previous
#include <cuda_runtime.h>
#include <cuda_bf16.h>

// ----------------------------------------------------------------------------
// RelativeAttention2d  (B=16, C=256, H=32 -> N=1024, HEADS=8, HS=32)
// Round: ldmatrix-fed attention + fused QKV HMMA GEMM + 3-stage cp.async.
// Fix vs R13: attention Vsb stage offset (bytes-vs-elements mismatch).
// ----------------------------------------------------------------------------

namespace {
constexpr int BATCH = 16;
constexpr int PB    = 256 * 1024;
constexpr int HSZ   = BATCH * 8 * 32 * 1024;   // per-tensor head-layout elems
}

typedef unsigned int u32;

__device__ __nv_bfloat16 g_xnb[BATCH * PB];            // LN out  [16384][256]
__device__ __nv_bfloat16 g_ob [BATCH * PB];            // attn out [16384][256]
__device__ __nv_bfloat16 g_qkv[3 * HSZ];               // q,k,v  [b][h][d][tok]
__device__ __nv_bfloat16 g_wb[4 * 256 * 256];          // bf16 weights q,k,v,o
__device__ float         g_b3[768];                    // packed bq|bk|bv

// ------------------------------- helpers ------------------------------------
__device__ __forceinline__ u32 bf2(float a, float b) {
    __nv_bfloat162 t = __floats2bfloat162_rn(a, b);
    return *(u32*)&t;
}
__device__ __forceinline__ u32 pk2(const __nv_bfloat16* lo, const __nv_bfloat16* hi) {
    return (u32)*(const unsigned short*)lo | ((u32)*(const unsigned short*)hi << 16);
}
__device__ __forceinline__ void mma_bf16(float& c0, float& c1, float& c2, float& c3,
                                         u32 a0, u32 a1, u32 a2, u32 a3,
                                         u32 b0, u32 b1) {
    asm volatile(
        "mma.sync.aligned.m16n8k16.row.col.f32.bf16.bf16.f32 "
        "{%0,%1,%2,%3}, {%4,%5,%6,%7}, {%8,%9}, {%0,%1,%2,%3};"
        : "+f"(c0), "+f"(c1), "+f"(c2), "+f"(c3)
        : "r"(a0), "r"(a1), "r"(a2), "r"(a3), "r"(b0), "r"(b1));
}
__device__ __forceinline__ void ldsm4(u32& r0, u32& r1, u32& r2, u32& r3,
                                      const __nv_bfloat16* p) {
    u32 a = (u32)__cvta_generic_to_shared(p);
    asm volatile("ldmatrix.sync.aligned.m8n8.x4.shared.b16 {%0,%1,%2,%3}, [%4];"
                 : "=r"(r0), "=r"(r1), "=r"(r2), "=r"(r3) : "r"(a));
}
__device__ __forceinline__ void ldsm4t(u32& r0, u32& r1, u32& r2, u32& r3,
                                       const __nv_bfloat16* p) {
    u32 a = (u32)__cvta_generic_to_shared(p);
    asm volatile("ldmatrix.sync.aligned.m8n8.x4.trans.shared.b16 {%0,%1,%2,%3}, [%4];"
                 : "=r"(r0), "=r"(r1), "=r"(r2), "=r"(r3) : "r"(a));
}
__device__ __forceinline__ void cp16(u32 dst, const void* src) {
    asm volatile("cp.async.cg.shared.global [%0], [%1], 16;" :: "r"(dst), "l"(src));
}
#define CP_COMMIT()  asm volatile("cp.async.commit_group;")
#define CP_WAIT1()   asm volatile("cp.async.wait_group 1;")
#define CP_WAIT0()   asm volatile("cp.async.wait_group 0;")

// ------------------------------ LayerNorm (-> bf16) --------------------------
__global__ __launch_bounds__(256) void ln_kernel(const float* __restrict__ x,
                                                 const float* __restrict__ gamma,
                                                 const float* __restrict__ beta) {
    __shared__ float sg[256];
    __shared__ float sb[256];
    const int tid = threadIdx.x;
    sg[tid] = gamma[tid];
    sb[tid] = beta[tid];
    __syncthreads();

    const int b = blockIdx.y;
    const int p = blockIdx.x * 256 + tid;
    const float* xb = x + b * PB;

    float s = 0.f, ss = 0.f;
#pragma unroll 8
    for (int c = 0; c < 256; c++) {
        const float v = xb[c * 1024 + p];
        s += v;
        ss += v * v;
    }
    const float mu  = s * (1.0f / 256.0f);
    const float var = ss * (1.0f / 256.0f) - mu * mu;
    const float r   = rsqrtf(var + 1e-5f);

    __nv_bfloat16* ob = g_xnb + (size_t)b * PB;
#pragma unroll 8
    for (int c = 0; c < 256; c++) {
        const float v = xb[c * 1024 + p];
        ob[c * 1024 + p] = __float2bfloat16((v - mu) * r * sg[c] + sb[c]);
    }
}

// ---------------- weight fp32->bf16 + bias packing ---------------------------
__global__ __launch_bounds__(256) void cvt_kernel(const float* __restrict__ w0,
                                                  const float* __restrict__ w1,
                                                  const float* __restrict__ w2,
                                                  const float* __restrict__ w3) {
    const float* src = (blockIdx.y == 0) ? w0 : (blockIdx.y == 1) ? w1
                     : (blockIdx.y == 2) ? w2 : w3;
    __nv_bfloat16* dst = g_wb + (size_t)blockIdx.y * 65536;
    const int i = (blockIdx.x * 256 + threadIdx.x) * 4;
    const float4 v = *(const float4*)&src[i];
    uint2 st;
    st.x = bf2(v.x, v.y);
    st.y = bf2(v.z, v.w);
    *(uint2*)&dst[i] = st;
}
__global__ void cvtb_kernel(const float* __restrict__ bq,
                            const float* __restrict__ bk,
                            const float* __restrict__ bv) {
    const float* s = (blockIdx.x == 0) ? bq : (blockIdx.x == 1) ? bk : bv;
    g_b3[blockIdx.x * 256 + threadIdx.x] = s[threadIdx.x];
}

// ------------------------- bf16 HMMA GEMM ------------------------------------
// C[R][col] = sum_k A[R][k] * W[col][k].   CTA 128x128, 8 warps, 3-stage pipe.
// outQ mode: bf16 head-layout scatter (col selects q/k/v tensor);
// outF mode: fp32 + bias + residual.
__device__ __forceinline__ void stq(__nv_bfloat16* dst, int R, int col,
                                    float v0, float v1) {
    const int t  = col >> 8;
    const int cc = col & 255;
    const int b  = R >> 10, r = R & 1023;
    const int h  = r >> 7;
    const int dh = (r >> 2) & 31;
    const int jb = r & 3;
    const size_t off = (size_t)t * HSZ +
                       ((size_t)((b * 8 + h) * 32 + dh) << 10) + (jb * 256 + cc);
    *(u32*)&dst[off] = bf2(v0, v1);
}

__global__ __launch_bounds__(256, 2) void gemm_bf16_kernel(
    const __nv_bfloat16* __restrict__ A,
    const __nv_bfloat16* __restrict__ Wb,
    const float* __restrict__ bias,
    __nv_bfloat16* __restrict__ outQ,
    float* __restrict__ outF,
    const float* __restrict__ Res)
{
    __shared__ __align__(16) __nv_bfloat16 As[3][3072];   // [128][24] per stage
    __shared__ __align__(16) __nv_bfloat16 Bs[3][3072];

    const int tid  = threadIdx.x;
    const int lane = tid & 31;
    const int w    = tid >> 5;
    const int g    = lane >> 2;
    const int tg   = lane & 3;
    const int bn   = blockIdx.x;
    const int bm   = blockIdx.y;
    const int warpM = (w & 3) * 32;
    const int warpN = (w >> 2) * 64;

    const int lrow  = tid >> 1;
    const int lhalf = (tid & 1) * 8;
    const __nv_bfloat16* Ag = A  + (size_t)(bm * 128 + lrow) * 256 + lhalf;
    const __nv_bfloat16* Bg = Wb + (size_t)(bn * 128 + lrow) * 256 + lhalf;
    const u32 sA = (u32)__cvta_generic_to_shared(&As[0][lrow * 24 + lhalf]);
    const u32 sB = (u32)__cvta_generic_to_shared(&Bs[0][lrow * 24 + lhalf]);

    float acc[2][8][4];
#pragma unroll
    for (int i = 0; i < 2; i++)
#pragma unroll
        for (int j = 0; j < 8; j++)
#pragma unroll
            for (int r = 0; r < 4; r++) acc[i][j][r] = 0.f;

    cp16(sA, Ag);             cp16(sB, Bg);             CP_COMMIT();
    cp16(sA + 6144, Ag + 16); cp16(sB + 6144, Bg + 16); CP_COMMIT();

    const int aRow = lane & 15;
    const int aCol = (lane >> 4) * 8;
    const int bRow = ((lane >> 4) << 3) + (lane & 7);
    const int bCol = ((lane >> 3) & 1) * 8;

    for (int ks = 0; ks < 16; ks++) {
        if (ks < 15) CP_WAIT1(); else CP_WAIT0();
        __syncthreads();

        const int buf = ks - (ks / 3) * 3;   // ks % 3
        const __nv_bfloat16* sa = As[buf];
        const __nv_bfloat16* sb = Bs[buf];
        u32 a0[4], a1[4];
        ldsm4(a0[0], a0[1], a0[2], a0[3], sa + (warpM + aRow) * 24 + aCol);
        ldsm4(a1[0], a1[1], a1[2], a1[3], sa + (warpM + 16 + aRow) * 24 + aCol);
#pragma unroll
        for (int nf16 = 0; nf16 < 4; nf16++) {
            u32 b0, b1, b2, b3;
            ldsm4(b0, b1, b2, b3, sb + (warpN + nf16 * 16 + bRow) * 24 + bCol);
            float* cl0 = acc[0][nf16 * 2];
            float* ch0 = acc[0][nf16 * 2 + 1];
            float* cl1 = acc[1][nf16 * 2];
            float* ch1 = acc[1][nf16 * 2 + 1];
            mma_bf16(cl0[0], cl0[1], cl0[2], cl0[3], a0[0], a0[1], a0[2], a0[3], b0, b1);
            mma_bf16(ch0[0], ch0[1], ch0[2], ch0[3], a0[0], a0[1], a0[2], a0[3], b2, b3);
            mma_bf16(cl1[0], cl1[1], cl1[2], cl1[3], a1[0], a1[1], a1[2], a1[3], b0, b1);
            mma_bf16(ch1[0], ch1[1], ch1[2], ch1[3], a1[0], a1[1], a1[2], a1[3], b2, b3);
        }

        if (ks + 2 < 16) {   // issue after compute: stage (ks+2)%3 is free now
            const int nb = (ks + 2) - ((ks + 2) / 3) * 3;
            cp16(sA + nb * 6144, Ag + (ks + 2) * 16);
            cp16(sB + nb * 6144, Bg + (ks + 2) * 16);
            CP_COMMIT();
        }
    }

    // epilogue
#pragma unroll
    for (int mi = 0; mi < 2; mi++) {
        const int R0 = bm * 128 + warpM + mi * 16 + g;
#pragma unroll
        for (int nf = 0; nf < 8; nf++) {
            const int col = bn * 128 + warpN + nf * 8 + 2 * tg;
            const float2 bv = *(const float2*)&bias[col];
            const float v0 = acc[mi][nf][0] + bv.x;
            const float v1 = acc[mi][nf][1] + bv.y;
            const float v2 = acc[mi][nf][2] + bv.x;
            const float v3 = acc[mi][nf][3] + bv.y;
            if (outQ != nullptr) {
                stq(outQ, R0,     col, v0, v1);
                stq(outQ, R0 + 8, col, v2, v3);
            } else {
                const size_t i0 = (size_t)R0 * 256 + col;
                const size_t i1 = i0 + 8 * 256;
                const float2 r0 = *(const float2*)&Res[i0];
                const float2 r1 = *(const float2*)&Res[i1];
                *(float2*)&outF[i0] = make_float2(v0 + r0.x, v1 + r0.y);
                *(float2*)&outF[i1] = make_float2(v2 + r1.x, v3 + r1.y);
            }
        }
    }
}

// ------------------------------ Attention (bf16 HMMA) ------------------------
// CTA = (128-query tile, head, batch), 8 warps.  3-stage cp.async K/V pipe,
// ldmatrix.x4(.trans) fragment feeds, analytic rel-bias, key-axis softmax.
// Stage layout (bytes, per stage): K tile 4608 | V tile 4608  (stride 9216).
// dyn smem: relb 15888B | Qs 8192B | 3 x 9216B = 51728B total
__global__ __launch_bounds__(256) void attn_kernel(const float* __restrict__ rel_bias) {
    extern __shared__ __align__(16) unsigned char smraw[];
    float* relb = (float*)smraw;                                  // 3972 floats
    __nv_bfloat16* Qs  = (__nv_bfloat16*)(smraw + 15888);         // [32][128]
    __nv_bfloat16* KVs = (__nv_bfloat16*)(smraw + 15888 + 8192);  // 3 stages

    const int tid  = threadIdx.x;
    const int w    = tid >> 5;
    const int lane = tid & 31;
    const int g    = lane >> 2;
    const int tg   = lane & 3;

    const int m0 = blockIdx.x * 128;
    const int h  = blockIdx.y;
    const int b  = blockIdx.z;
    const int bh = b * 8 + h;

    const __nv_bfloat16* qh = g_qkv + (size_t)bh * 32768;
    const __nv_bfloat16* kh = g_qkv + (size_t)HSZ     + (size_t)bh * 32768;
    const __nv_bfloat16* vh = g_qkv + (size_t)2 * HSZ + (size_t)bh * 32768;

    // K/V tile cp.async (per thread: one 16B chunk each)
    const int ld   = tid >> 3;
    const int noff = (tid & 7) * 8;
    const u32 sK = (u32)__cvta_generic_to_shared(KVs + ld * 72 + noff);
    const u32 sV = sK + 4608;
    const __nv_bfloat16* kg = kh + (size_t)ld * 1024 + noff;
    const __nv_bfloat16* vg = vh + (size_t)ld * 1024 + noff;

    cp16(sK, kg);             cp16(sV, vg);             CP_COMMIT();   // tile 0
    cp16(sK + 9216, kg + 64); cp16(sV + 9216, vg + 64); CP_COMMIT();   // tile 1

    // rel-bias table + Q tile
    const float* rb = rel_bias + h * 3969;
    for (int i = tid; i < 3969; i += 256) relb[i] = rb[i];
    {
        const int d    = tid >> 3;
        const int moff = (tid & 7) * 16;
        const uint4* src = (const uint4*)(qh + (size_t)d * 1024 + m0 + moff);
        *(uint4*)(Qs + d * 128 + moff)     = src[0];
        *(uint4*)(Qs + d * 128 + moff + 8) = src[1];
    }
    __syncthreads();

    // Q A-fragments (once per CTA)
    const int mloc_lo = w * 16 + g;
    const int mloc_hi = mloc_lo + 8;
    u32 qa[2][4];
#pragma unroll
    for (int kc = 0; kc < 2; kc++) {
        const int k0 = kc * 16 + tg * 2;
        qa[kc][0] = pk2(&Qs[(k0 + 0) * 128 + mloc_lo], &Qs[(k0 + 1) * 128 + mloc_lo]);
        qa[kc][1] = pk2(&Qs[(k0 + 0) * 128 + mloc_hi], &Qs[(k0 + 1) * 128 + mloc_hi]);
        qa[kc][2] = pk2(&Qs[(k0 + 8) * 128 + mloc_lo], &Qs[(k0 + 9) * 128 + mloc_lo]);
        qa[kc][3] = pk2(&Qs[(k0 + 8) * 128 + mloc_hi], &Qs[(k0 + 9) * 128 + mloc_hi]);
    }

    const int m_lo = m0 + mloc_lo;
    const int m_hi = m_lo + 8;
    const int Clo  = 1984 - (m_lo >> 5) * 63 - (m_lo & 31);
    const int Chi  = 1984 - (m_hi >> 5) * 63 - (m_hi & 31);

    // ldmatrix lane addressing offsets
    const int i2 = lane >> 3;
    const int r8 = lane & 7;
    const int rowKb = ((i2 & 1) << 3) + r8;    // + kc*16  (trans, K)
    const int colKb = (i2 >> 1) << 3;          // + q4*16
    const int rowVb = ((i2 >> 1) << 3) + r8;   // + dfp*16 (non-trans, V)
    const int colVb = (i2 & 1) << 3;           // + f*16

    float oc[4][4];
#pragma unroll
    for (int df = 0; df < 4; df++)
#pragma unroll
        for (int r = 0; r < 4; r++) oc[df][r] = 0.f;
    float rs_lo = 0.f, rs_hi = 0.f;

    for (int nt = 0; nt < 16; nt++) {
        if (nt < 15) CP_WAIT1(); else CP_WAIT0();
        __syncthreads();

        const int st = nt - (nt / 3) * 3;   // nt % 3
        const __nv_bfloat16* Ksb = KVs + st * 4608;   // 4608 elem = 9216 B stride
        const __nv_bfloat16* Vsb = Ksb + 2304;        // V is 4608 BYTES after K
        const int n0 = nt * 64;

        // ---- QK: S frags + exp epilogue -> pa ------------------------------
        u32 pa[4][4];
#pragma unroll
        for (int q4 = 0; q4 < 4; q4++) {
            u32 kf0[4], kf1[4];
            ldsm4t(kf0[0], kf0[1], kf0[2], kf0[3],
                   Ksb + (rowKb) * 72 + q4 * 16 + colKb);
            ldsm4t(kf1[0], kf1[1], kf1[2], kf1[3],
                   Ksb + (16 + rowKb) * 72 + q4 * 16 + colKb);
#pragma unroll
            for (int half = 0; half < 2; half++) {
                const int nf = q4 * 2 + half;
                float c0 = 0.f, c1 = 0.f, c2 = 0.f, c3 = 0.f;
                mma_bf16(c0, c1, c2, c3, qa[0][0], qa[0][1], qa[0][2], qa[0][3],
                         kf0[half * 2], kf0[half * 2 + 1]);
                mma_bf16(c0, c1, c2, c3, qa[1][0], qa[1][1], qa[1][2], qa[1][3],
                         kf1[half * 2], kf1[half * 2 + 1]);
                const int n1 = n0 + nf * 8 + tg * 2;
                const int n2 = n1 + 1;
                const int i1 = (n1 >> 5) * 63 + (n1 & 31);
                const int ix2 = (n2 >> 5) * 63 + (n2 & 31);
                const float p0 = __expf(fmaf(c0, 0.0625f, relb[i1  + Clo]));
                const float p1 = __expf(fmaf(c1, 0.0625f, relb[ix2 + Clo]));
                const float p2 = __expf(fmaf(c2, 0.0625f, relb[i1  + Chi]));
                const float p3 = __expf(fmaf(c3, 0.0625f, relb[ix2 + Chi]));
                rs_lo += p0 + p1;
                rs_hi += p2 + p3;
                if (half == 0) {
                    pa[q4][0] = bf2(p0, p1);
                    pa[q4][1] = bf2(p2, p3);
                } else {
                    pa[q4][2] = bf2(p0, p1);
                    pa[q4][3] = bf2(p2, p3);
                }
            }
        }

        // ---- PV: O += P V ---------------------------------------------------
#pragma unroll
        for (int f = 0; f < 4; f++) {
#pragma unroll
            for (int dfp = 0; dfp < 2; dfp++) {
                u32 vf[4];
                ldsm4(vf[0], vf[1], vf[2], vf[3],
                      Vsb + (dfp * 16 + rowVb) * 72 + f * 16 + colVb);
                const int df = dfp * 2;
                mma_bf16(oc[df][0], oc[df][1], oc[df][2], oc[df][3],
                         pa[f][0], pa[f][1], pa[f][2], pa[f][3], vf[0], vf[1]);
                mma_bf16(oc[df + 1][0], oc[df + 1][1], oc[df + 1][2], oc[df + 1][3],
                         pa[f][0], pa[f][1], pa[f][2], pa[f][3], vf[2], vf[3]);
            }
        }

        if (nt + 2 < 16) {   // issue after compute: stage (nt+2)%3 is free
            const int nb = (nt + 2) - ((nt + 2) / 3) * 3;
            cp16(sK + nb * 9216, kg + (nt + 2) * 64);
            cp16(sV + nb * 9216, vg + (nt + 2) * 64);
            CP_COMMIT();
        }
    }

    rs_lo += __shfl_xor_sync(0xffffffffu, rs_lo, 1);
    rs_lo += __shfl_xor_sync(0xffffffffu, rs_lo, 2);
    rs_hi += __shfl_xor_sync(0xffffffffu, rs_hi, 1);
    rs_hi += __shfl_xor_sync(0xffffffffu, rs_hi, 2);
    const float inv_lo = 1.0f / rs_lo;
    const float inv_hi = 1.0f / rs_hi;

    __nv_bfloat16* OL = g_ob + (size_t)b * PB;
    const int jblk = m0 >> 8;
    const int mclo = m_lo & 255;
    const int mchi = m_hi & 255;
#pragma unroll
    for (int df = 0; df < 4; df++) {
        const int d1 = df * 8 + tg * 2;
        const int d2 = d1 + 1;
        const int r1 = h * 128 + 4 * d1 + jblk;
        const int r2 = h * 128 + 4 * d2 + jblk;
        OL[r1 * 256 + mclo] = __float2bfloat16(oc[df][0] * inv_lo);
        OL[r2 * 256 + mclo] = __float2bfloat16(oc[df][1] * inv_lo);
        OL[r1 * 256 + mchi] = __float2bfloat16(oc[df][2] * inv_hi);
        OL[r2 * 256 + mchi] = __float2bfloat16(oc[df][3] * inv_hi);
    }
}

// ------------------------------ Launch --------------------------------------
extern "C" void kernel_launch(void* const* d_in, const int* in_sizes, int n_in,
                              void* d_out, int out_size) {
    const float* x        = (const float*)d_in[0];
    const float* ln_g     = (const float*)d_in[1];
    const float* ln_b     = (const float*)d_in[2];
    const float* wq       = (const float*)d_in[3];
    const float* bq       = (const float*)d_in[4];
    const float* wk       = (const float*)d_in[5];
    const float* bk       = (const float*)d_in[6];
    const float* wv       = (const float*)d_in[7];
    const float* bv       = (const float*)d_in[8];
    const float* wo       = (const float*)d_in[9];
    const float* bo       = (const float*)d_in[10];
    const float* rel_bias = (const float*)d_in[11];
    float* out = (float*)d_out;
    (void)in_sizes; (void)n_in; (void)out_size;

    __nv_bfloat16 *p_xnb, *p_ob, *p_qkv, *p_wb;
    float* p_b3;
    cudaGetSymbolAddress((void**)&p_xnb, g_xnb);
    cudaGetSymbolAddress((void**)&p_ob,  g_ob);
    cudaGetSymbolAddress((void**)&p_qkv, g_qkv);
    cudaGetSymbolAddress((void**)&p_wb,  g_wb);
    cudaGetSymbolAddress((void**)&p_b3,  g_b3);

    ln_kernel<<<dim3(4, BATCH), 256>>>(x, ln_g, ln_b);
    cvt_kernel<<<dim3(64, 4), 256>>>(wq, wk, wv, wo);
    cvtb_kernel<<<3, 256>>>(bq, bk, bv);

    // fused QKV: W = g_wb[0..3*65536) viewed as [768][256]
    gemm_bf16_kernel<<<dim3(6, 128), 256>>>(p_xnb, p_wb, p_b3, p_qkv, nullptr, nullptr);

    const int smem_bytes = 15888 + 8192 + 3 * 9216;   // 51728
    cudaFuncSetAttribute((const void*)attn_kernel,
                         cudaFuncAttributeMaxDynamicSharedMemorySize, smem_bytes);
    attn_kernel<<<dim3(8, 8, BATCH), 256, smem_bytes>>>(rel_bias);

    gemm_bf16_kernel<<<dim3(2, 128), 256>>>(p_ob, p_wb + 3 * 65536, bo, nullptr, out, x);
}

// round 15
// speedup vs baseline: 6.2028x; 1.0832x over previous
#include <cuda_runtime.h>
#include <cuda_bf16.h>

// ----------------------------------------------------------------------------
// RelativeAttention2d  (B=16, C=256, H=32 -> N=1024, HEADS=8, HS=32)
// Round: k=32 GEMM slices (half the barriers), LN unroll-32 MLP,
//        exp2f attention with log2e-folded bias table.
// ----------------------------------------------------------------------------

namespace {
constexpr int BATCH = 16;
constexpr int PB    = 256 * 1024;
constexpr int HSZ   = BATCH * 8 * 32 * 1024;   // per-tensor head-layout elems
}

typedef unsigned int u32;

__device__ __nv_bfloat16 g_xnb[BATCH * PB];            // LN out  [16384][256]
__device__ __nv_bfloat16 g_ob [BATCH * PB];            // attn out [16384][256]
__device__ __nv_bfloat16 g_qkv[3 * HSZ];               // q,k,v  [b][h][d][tok]
__device__ __nv_bfloat16 g_wb[4 * 256 * 256];          // bf16 weights q,k,v,o
__device__ float         g_b3[768];                    // packed bq|bk|bv

// ------------------------------- helpers ------------------------------------
__device__ __forceinline__ u32 bf2(float a, float b) {
    __nv_bfloat162 t = __floats2bfloat162_rn(a, b);
    return *(u32*)&t;
}
__device__ __forceinline__ u32 pk2(const __nv_bfloat16* lo, const __nv_bfloat16* hi) {
    return (u32)*(const unsigned short*)lo | ((u32)*(const unsigned short*)hi << 16);
}
__device__ __forceinline__ void mma_bf16(float& c0, float& c1, float& c2, float& c3,
                                         u32 a0, u32 a1, u32 a2, u32 a3,
                                         u32 b0, u32 b1) {
    asm volatile(
        "mma.sync.aligned.m16n8k16.row.col.f32.bf16.bf16.f32 "
        "{%0,%1,%2,%3}, {%4,%5,%6,%7}, {%8,%9}, {%0,%1,%2,%3};"
        : "+f"(c0), "+f"(c1), "+f"(c2), "+f"(c3)
        : "r"(a0), "r"(a1), "r"(a2), "r"(a3), "r"(b0), "r"(b1));
}
__device__ __forceinline__ void ldsm4(u32& r0, u32& r1, u32& r2, u32& r3,
                                      const __nv_bfloat16* p) {
    u32 a = (u32)__cvta_generic_to_shared(p);
    asm volatile("ldmatrix.sync.aligned.m8n8.x4.shared.b16 {%0,%1,%2,%3}, [%4];"
                 : "=r"(r0), "=r"(r1), "=r"(r2), "=r"(r3) : "r"(a));
}
__device__ __forceinline__ void ldsm4t(u32& r0, u32& r1, u32& r2, u32& r3,
                                       const __nv_bfloat16* p) {
    u32 a = (u32)__cvta_generic_to_shared(p);
    asm volatile("ldmatrix.sync.aligned.m8n8.x4.trans.shared.b16 {%0,%1,%2,%3}, [%4];"
                 : "=r"(r0), "=r"(r1), "=r"(r2), "=r"(r3) : "r"(a));
}
__device__ __forceinline__ void cp16(u32 dst, const void* src) {
    asm volatile("cp.async.cg.shared.global [%0], [%1], 16;" :: "r"(dst), "l"(src));
}
#define CP_COMMIT()  asm volatile("cp.async.commit_group;")
#define CP_WAIT1()   asm volatile("cp.async.wait_group 1;")
#define CP_WAIT0()   asm volatile("cp.async.wait_group 0;")

// ------------------------------ LayerNorm (-> bf16) --------------------------
__global__ __launch_bounds__(256) void ln_kernel(const float* __restrict__ x,
                                                 const float* __restrict__ gamma,
                                                 const float* __restrict__ beta) {
    __shared__ float sg[256];
    __shared__ float sb[256];
    const int tid = threadIdx.x;
    sg[tid] = gamma[tid];
    sb[tid] = beta[tid];
    __syncthreads();

    const int b = blockIdx.y;
    const int p = blockIdx.x * 256 + tid;
    const float* xb = x + b * PB;

    float s = 0.f, ss = 0.f;
#pragma unroll 32
    for (int c = 0; c < 256; c++) {
        const float v = xb[c * 1024 + p];
        s += v;
        ss += v * v;
    }
    const float mu  = s * (1.0f / 256.0f);
    const float var = ss * (1.0f / 256.0f) - mu * mu;
    const float r   = rsqrtf(var + 1e-5f);

    __nv_bfloat16* ob = g_xnb + (size_t)b * PB;
#pragma unroll 32
    for (int c = 0; c < 256; c++) {
        const float v = xb[c * 1024 + p];
        ob[c * 1024 + p] = __float2bfloat16((v - mu) * r * sg[c] + sb[c]);
    }
}

// ---------------- weight fp32->bf16 + bias packing ---------------------------
__global__ __launch_bounds__(256) void cvt_kernel(const float* __restrict__ w0,
                                                  const float* __restrict__ w1,
                                                  const float* __restrict__ w2,
                                                  const float* __restrict__ w3) {
    const float* src = (blockIdx.y == 0) ? w0 : (blockIdx.y == 1) ? w1
                     : (blockIdx.y == 2) ? w2 : w3;
    __nv_bfloat16* dst = g_wb + (size_t)blockIdx.y * 65536;
    const int i = (blockIdx.x * 256 + threadIdx.x) * 4;
    const float4 v = *(const float4*)&src[i];
    uint2 st;
    st.x = bf2(v.x, v.y);
    st.y = bf2(v.z, v.w);
    *(uint2*)&dst[i] = st;
}
__global__ void cvtb_kernel(const float* __restrict__ bq,
                            const float* __restrict__ bk,
                            const float* __restrict__ bv) {
    const float* s = (blockIdx.x == 0) ? bq : (blockIdx.x == 1) ? bk : bv;
    g_b3[blockIdx.x * 256 + threadIdx.x] = s[threadIdx.x];
}

// ------------------------- bf16 HMMA GEMM (k=32 slices) ----------------------
// C[R][col] = sum_k A[R][k] * W[col][k].  CTA 128x128, 8 warps, 3-stage pipe,
// 8 k-iterations of 32.  Stage row stride 40 el (80 B) -> conflict-free ldsm.
__device__ __forceinline__ void stq(__nv_bfloat16* dst, int R, int col,
                                    float v0, float v1) {
    const int t  = col >> 8;
    const int cc = col & 255;
    const int b  = R >> 10, r = R & 1023;
    const int h  = r >> 7;
    const int dh = (r >> 2) & 31;
    const int jb = r & 3;
    const size_t off = (size_t)t * HSZ +
                       ((size_t)((b * 8 + h) * 32 + dh) << 10) + (jb * 256 + cc);
    *(u32*)&dst[off] = bf2(v0, v1);
}

__global__ __launch_bounds__(256, 2) void gemm_bf16_kernel(
    const __nv_bfloat16* __restrict__ A,
    const __nv_bfloat16* __restrict__ Wb,
    const float* __restrict__ bias,
    __nv_bfloat16* __restrict__ outQ,
    float* __restrict__ outF,
    const float* __restrict__ Res)
{
    __shared__ __align__(16) __nv_bfloat16 As[3][5120];   // [128][40] per stage
    __shared__ __align__(16) __nv_bfloat16 Bs[3][5120];

    const int tid  = threadIdx.x;
    const int lane = tid & 31;
    const int w    = tid >> 5;
    const int g    = lane >> 2;
    const int tg   = lane & 3;
    const int bn   = blockIdx.x;
    const int bm   = blockIdx.y;
    const int warpM = (w & 3) * 32;
    const int warpN = (w >> 2) * 64;

    const int lrow = tid >> 1;           // tile row 0..127
    const int co   = (tid & 1) * 16;     // k offset 0 or 16 (8 el per cp16)
    const __nv_bfloat16* Ag = A  + (size_t)(bm * 128 + lrow) * 256 + co;
    const __nv_bfloat16* Bg = Wb + (size_t)(bn * 128 + lrow) * 256 + co;
    const u32 sA = (u32)__cvta_generic_to_shared(&As[0][lrow * 40 + co]);
    const u32 sB = (u32)__cvta_generic_to_shared(&Bs[0][lrow * 40 + co]);

    float acc[2][8][4];
#pragma unroll
    for (int i = 0; i < 2; i++)
#pragma unroll
        for (int j = 0; j < 8; j++)
#pragma unroll
            for (int r = 0; r < 4; r++) acc[i][j][r] = 0.f;

    // prologue: stages 0 and 1 (k0 = 0, 32)
    cp16(sA, Ag);                 cp16(sA + 16, Ag + 8);
    cp16(sB, Bg);                 cp16(sB + 16, Bg + 8);
    CP_COMMIT();
    cp16(sA + 10240, Ag + 32);    cp16(sA + 10240 + 16, Ag + 40);
    cp16(sB + 10240, Bg + 32);    cp16(sB + 10240 + 16, Bg + 40);
    CP_COMMIT();

    const int aRow = lane & 15;
    const int aCol = (lane >> 4) * 8;
    const int bRow = ((lane >> 4) << 3) + (lane & 7);
    const int bCol = ((lane >> 3) & 1) * 8;

    for (int ks = 0; ks < 8; ks++) {
        if (ks < 7) CP_WAIT1(); else CP_WAIT0();
        __syncthreads();

        const int buf = ks - (ks / 3) * 3;   // ks % 3
        const __nv_bfloat16* sa = As[buf];
        const __nv_bfloat16* sb = Bs[buf];
#pragma unroll
        for (int kc = 0; kc < 2; kc++) {
            const int kb = kc * 16;
            u32 a0[4], a1[4];
            ldsm4(a0[0], a0[1], a0[2], a0[3], sa + (warpM + aRow) * 40 + kb + aCol);
            ldsm4(a1[0], a1[1], a1[2], a1[3], sa + (warpM + 16 + aRow) * 40 + kb + aCol);
#pragma unroll
            for (int nf16 = 0; nf16 < 4; nf16++) {
                u32 b0, b1, b2, b3;
                ldsm4(b0, b1, b2, b3, sb + (warpN + nf16 * 16 + bRow) * 40 + kb + bCol);
                float* cl0 = acc[0][nf16 * 2];
                float* ch0 = acc[0][nf16 * 2 + 1];
                float* cl1 = acc[1][nf16 * 2];
                float* ch1 = acc[1][nf16 * 2 + 1];
                mma_bf16(cl0[0], cl0[1], cl0[2], cl0[3], a0[0], a0[1], a0[2], a0[3], b0, b1);
                mma_bf16(ch0[0], ch0[1], ch0[2], ch0[3], a0[0], a0[1], a0[2], a0[3], b2, b3);
                mma_bf16(cl1[0], cl1[1], cl1[2], cl1[3], a1[0], a1[1], a1[2], a1[3], b0, b1);
                mma_bf16(ch1[0], ch1[1], ch1[2], ch1[3], a1[0], a1[1], a1[2], a1[3], b2, b3);
            }
        }

        if (ks + 2 < 8) {   // issue after compute: stage (ks+2)%3 is free now
            const int nb = (ks + 2) - ((ks + 2) / 3) * 3;
            const int k0 = (ks + 2) * 32;
            cp16(sA + nb * 10240,      Ag + k0);
            cp16(sA + nb * 10240 + 16, Ag + k0 + 8);
            cp16(sB + nb * 10240,      Bg + k0);
            cp16(sB + nb * 10240 + 16, Bg + k0 + 8);
            CP_COMMIT();
        }
    }

    // epilogue
#pragma unroll
    for (int mi = 0; mi < 2; mi++) {
        const int R0 = bm * 128 + warpM + mi * 16 + g;
#pragma unroll
        for (int nf = 0; nf < 8; nf++) {
            const int col = bn * 128 + warpN + nf * 8 + 2 * tg;
            const float2 bv = *(const float2*)&bias[col];
            const float v0 = acc[mi][nf][0] + bv.x;
            const float v1 = acc[mi][nf][1] + bv.y;
            const float v2 = acc[mi][nf][2] + bv.x;
            const float v3 = acc[mi][nf][3] + bv.y;
            if (outQ != nullptr) {
                stq(outQ, R0,     col, v0, v1);
                stq(outQ, R0 + 8, col, v2, v3);
            } else {
                const size_t i0 = (size_t)R0 * 256 + col;
                const size_t i1 = i0 + 8 * 256;
                const float2 r0 = *(const float2*)&Res[i0];
                const float2 r1 = *(const float2*)&Res[i1];
                *(float2*)&outF[i0] = make_float2(v0 + r0.x, v1 + r0.y);
                *(float2*)&outF[i1] = make_float2(v2 + r1.x, v3 + r1.y);
            }
        }
    }
}

// ------------------------------ Attention (bf16 HMMA) ------------------------
// CTA = (128-query tile, head, batch), 8 warps.  3-stage cp.async K/V pipe,
// ldmatrix feeds, analytic rel-bias (table pre-scaled by log2e), exp2f.
// Stage layout (bytes, per stage): K tile 4608 | V tile 4608  (stride 9216).
// dyn smem: relb 15888B | Qs 8192B | 3 x 9216B = 51728B total
__global__ __launch_bounds__(256) void attn_kernel(const float* __restrict__ rel_bias) {
    extern __shared__ __align__(16) unsigned char smraw[];
    float* relb = (float*)smraw;                                  // 3972 floats
    __nv_bfloat16* Qs  = (__nv_bfloat16*)(smraw + 15888);         // [32][128]
    __nv_bfloat16* KVs = (__nv_bfloat16*)(smraw + 15888 + 8192);  // 3 stages

    const int tid  = threadIdx.x;
    const int w    = tid >> 5;
    const int lane = tid & 31;
    const int g    = lane >> 2;
    const int tg   = lane & 3;

    const int m0 = blockIdx.x * 128;
    const int h  = blockIdx.y;
    const int b  = blockIdx.z;
    const int bh = b * 8 + h;

    const __nv_bfloat16* qh = g_qkv + (size_t)bh * 32768;
    const __nv_bfloat16* kh = g_qkv + (size_t)HSZ     + (size_t)bh * 32768;
    const __nv_bfloat16* vh = g_qkv + (size_t)2 * HSZ + (size_t)bh * 32768;

    // K/V tile cp.async (per thread: one 16B chunk each)
    const int ld   = tid >> 3;
    const int noff = (tid & 7) * 8;
    const u32 sK = (u32)__cvta_generic_to_shared(KVs + ld * 72 + noff);
    const u32 sV = sK + 4608;
    const __nv_bfloat16* kg = kh + (size_t)ld * 1024 + noff;
    const __nv_bfloat16* vg = vh + (size_t)ld * 1024 + noff;

    cp16(sK, kg);             cp16(sV, vg);             CP_COMMIT();   // tile 0
    cp16(sK + 9216, kg + 64); cp16(sV + 9216, vg + 64); CP_COMMIT();   // tile 1

    // rel-bias table (pre-multiplied by log2e for exp2f) + Q tile
    const float* rb = rel_bias + h * 3969;
    for (int i = tid; i < 3969; i += 256) relb[i] = rb[i] * 1.4426950408889634f;
    {
        const int d    = tid >> 3;
        const int moff = (tid & 7) * 16;
        const uint4* src = (const uint4*)(qh + (size_t)d * 1024 + m0 + moff);
        *(uint4*)(Qs + d * 128 + moff)     = src[0];
        *(uint4*)(Qs + d * 128 + moff + 8) = src[1];
    }
    __syncthreads();

    // Q A-fragments (once per CTA)
    const int mloc_lo = w * 16 + g;
    const int mloc_hi = mloc_lo + 8;
    u32 qa[2][4];
#pragma unroll
    for (int kc = 0; kc < 2; kc++) {
        const int k0 = kc * 16 + tg * 2;
        qa[kc][0] = pk2(&Qs[(k0 + 0) * 128 + mloc_lo], &Qs[(k0 + 1) * 128 + mloc_lo]);
        qa[kc][1] = pk2(&Qs[(k0 + 0) * 128 + mloc_hi], &Qs[(k0 + 1) * 128 + mloc_hi]);
        qa[kc][2] = pk2(&Qs[(k0 + 8) * 128 + mloc_lo], &Qs[(k0 + 9) * 128 + mloc_lo]);
        qa[kc][3] = pk2(&Qs[(k0 + 8) * 128 + mloc_hi], &Qs[(k0 + 9) * 128 + mloc_hi]);
    }

    const int m_lo = m0 + mloc_lo;
    const int m_hi = m_lo + 8;
    const int Clo  = 1984 - (m_lo >> 5) * 63 - (m_lo & 31);
    const int Chi  = 1984 - (m_hi >> 5) * 63 - (m_hi & 31);

    // ldmatrix lane addressing offsets
    const int i2 = lane >> 3;
    const int r8 = lane & 7;
    const int rowKb = ((i2 & 1) << 3) + r8;    // + kc*16  (trans, K)
    const int colKb = (i2 >> 1) << 3;          // + q4*16
    const int rowVb = ((i2 >> 1) << 3) + r8;   // + dfp*16 (non-trans, V)
    const int colVb = (i2 & 1) << 3;           // + f*16

    const float lscale = 0.0625f * 1.4426950408889634f;   // /16, in log2 domain

    float oc[4][4];
#pragma unroll
    for (int df = 0; df < 4; df++)
#pragma unroll
        for (int r = 0; r < 4; r++) oc[df][r] = 0.f;
    float rs_lo = 0.f, rs_hi = 0.f;

    for (int nt = 0; nt < 16; nt++) {
        if (nt < 15) CP_WAIT1(); else CP_WAIT0();
        __syncthreads();

        const int st = nt - (nt / 3) * 3;   // nt % 3
        const __nv_bfloat16* Ksb = KVs + st * 4608;   // 4608 el = 9216 B stride
        const __nv_bfloat16* Vsb = Ksb + 2304;        // V is 4608 BYTES after K
        const int n0 = nt * 64;

        // ---- QK: S frags + exp epilogue -> pa ------------------------------
        u32 pa[4][4];
#pragma unroll
        for (int q4 = 0; q4 < 4; q4++) {
            u32 kf0[4], kf1[4];
            ldsm4t(kf0[0], kf0[1], kf0[2], kf0[3],
                   Ksb + (rowKb) * 72 + q4 * 16 + colKb);
            ldsm4t(kf1[0], kf1[1], kf1[2], kf1[3],
                   Ksb + (16 + rowKb) * 72 + q4 * 16 + colKb);
#pragma unroll
            for (int half = 0; half < 2; half++) {
                const int nf = q4 * 2 + half;
                float c0 = 0.f, c1 = 0.f, c2 = 0.f, c3 = 0.f;
                mma_bf16(c0, c1, c2, c3, qa[0][0], qa[0][1], qa[0][2], qa[0][3],
                         kf0[half * 2], kf0[half * 2 + 1]);
                mma_bf16(c0, c1, c2, c3, qa[1][0], qa[1][1], qa[1][2], qa[1][3],
                         kf1[half * 2], kf1[half * 2 + 1]);
                const int n1 = n0 + nf * 8 + tg * 2;
                const int n2 = n1 + 1;
                const int i1 = (n1 >> 5) * 63 + (n1 & 31);
                const int ix2 = (n2 >> 5) * 63 + (n2 & 31);
                const float p0 = exp2f(fmaf(c0, lscale, relb[i1  + Clo]));
                const float p1 = exp2f(fmaf(c1, lscale, relb[ix2 + Clo]));
                const float p2 = exp2f(fmaf(c2, lscale, relb[i1  + Chi]));
                const float p3 = exp2f(fmaf(c3, lscale, relb[ix2 + Chi]));
                rs_lo += p0 + p1;
                rs_hi += p2 + p3;
                if (half == 0) {
                    pa[q4][0] = bf2(p0, p1);
                    pa[q4][1] = bf2(p2, p3);
                } else {
                    pa[q4][2] = bf2(p0, p1);
                    pa[q4][3] = bf2(p2, p3);
                }
            }
        }

        // ---- PV: O += P V ---------------------------------------------------
#pragma unroll
        for (int f = 0; f < 4; f++) {
#pragma unroll
            for (int dfp = 0; dfp < 2; dfp++) {
                u32 vf[4];
                ldsm4(vf[0], vf[1], vf[2], vf[3],
                      Vsb + (dfp * 16 + rowVb) * 72 + f * 16 + colVb);
                const int df = dfp * 2;
                mma_bf16(oc[df][0], oc[df][1], oc[df][2], oc[df][3],
                         pa[f][0], pa[f][1], pa[f][2], pa[f][3], vf[0], vf[1]);
                mma_bf16(oc[df + 1][0], oc[df + 1][1], oc[df + 1][2], oc[df + 1][3],
                         pa[f][0], pa[f][1], pa[f][2], pa[f][3], vf[2], vf[3]);
            }
        }

        if (nt + 2 < 16) {   // issue after compute: stage (nt+2)%3 is free
            const int nb = (nt + 2) - ((nt + 2) / 3) * 3;
            cp16(sK + nb * 9216, kg + (nt + 2) * 64);
            cp16(sV + nb * 9216, vg + (nt + 2) * 64);
            CP_COMMIT();
        }
    }

    rs_lo += __shfl_xor_sync(0xffffffffu, rs_lo, 1);
    rs_lo += __shfl_xor_sync(0xffffffffu, rs_lo, 2);
    rs_hi += __shfl_xor_sync(0xffffffffu, rs_hi, 1);
    rs_hi += __shfl_xor_sync(0xffffffffu, rs_hi, 2);
    const float inv_lo = 1.0f / rs_lo;
    const float inv_hi = 1.0f / rs_hi;

    __nv_bfloat16* OL = g_ob + (size_t)b * PB;
    const int jblk = m0 >> 8;
    const int mclo = m_lo & 255;
    const int mchi = m_hi & 255;
#pragma unroll
    for (int df = 0; df < 4; df++) {
        const int d1 = df * 8 + tg * 2;
        const int d2 = d1 + 1;
        const int r1 = h * 128 + 4 * d1 + jblk;
        const int r2 = h * 128 + 4 * d2 + jblk;
        OL[r1 * 256 + mclo] = __float2bfloat16(oc[df][0] * inv_lo);
        OL[r2 * 256 + mclo] = __float2bfloat16(oc[df][1] * inv_lo);
        OL[r1 * 256 + mchi] = __float2bfloat16(oc[df][2] * inv_hi);
        OL[r2 * 256 + mchi] = __float2bfloat16(oc[df][3] * inv_hi);
    }
}

// ------------------------------ Launch --------------------------------------
extern "C" void kernel_launch(void* const* d_in, const int* in_sizes, int n_in,
                              void* d_out, int out_size) {
    const float* x        = (const float*)d_in[0];
    const float* ln_g     = (const float*)d_in[1];
    const float* ln_b     = (const float*)d_in[2];
    const float* wq       = (const float*)d_in[3];
    const float* bq       = (const float*)d_in[4];
    const float* wk       = (const float*)d_in[5];
    const float* bk       = (const float*)d_in[6];
    const float* wv       = (const float*)d_in[7];
    const float* bv       = (const float*)d_in[8];
    const float* wo       = (const float*)d_in[9];
    const float* bo       = (const float*)d_in[10];
    const float* rel_bias = (const float*)d_in[11];
    float* out = (float*)d_out;
    (void)in_sizes; (void)n_in; (void)out_size;

    __nv_bfloat16 *p_xnb, *p_ob, *p_qkv, *p_wb;
    float* p_b3;
    cudaGetSymbolAddress((void**)&p_xnb, g_xnb);
    cudaGetSymbolAddress((void**)&p_ob,  g_ob);
    cudaGetSymbolAddress((void**)&p_qkv, g_qkv);
    cudaGetSymbolAddress((void**)&p_wb,  g_wb);
    cudaGetSymbolAddress((void**)&p_b3,  g_b3);

    ln_kernel<<<dim3(4, BATCH), 256>>>(x, ln_g, ln_b);
    cvt_kernel<<<dim3(64, 4), 256>>>(wq, wk, wv, wo);
    cvtb_kernel<<<3, 256>>>(bq, bk, bv);

    // fused QKV: W = g_wb[0..3*65536) viewed as [768][256]
    gemm_bf16_kernel<<<dim3(6, 128), 256>>>(p_xnb, p_wb, p_b3, p_qkv, nullptr, nullptr);

    const int smem_bytes = 15888 + 8192 + 3 * 9216;   // 51728
    cudaFuncSetAttribute((const void*)attn_kernel,
                         cudaFuncAttributeMaxDynamicSharedMemorySize, smem_bytes);
    attn_kernel<<<dim3(8, 8, BATCH), 256, smem_bytes>>>(rel_bias);

    gemm_bf16_kernel<<<dim3(2, 128), 256>>>(p_ob, p_wb + 3 * 65536, bo, nullptr, out, x);
}